// round 4
// baseline (speedup 1.0000x reference)
#include <cuda_runtime.h>
#include <math.h>

// ---------------------------------------------------------------------------
// Problem constants: B=16, L=512, H=1024, G=2, NH=16, DH=64, FF=4096,
//                    DM=512, LG=256
// ---------------------------------------------------------------------------

// Scratch (device globals; allocation inside kernel_launch is forbidden)
__device__ float g_yc  [16u*512u*1024u];   // tf32-rounded copy of y
__device__ float g_wqkv[512u*1536u];       // packed tf32 Wq|Wk|Wv
__device__ float g_bqkv[1536u];
__device__ float g_wm  [1024u*1024u];
__device__ float g_w1  [1024u*4096u];
__device__ float g_w2  [2048u*512u];
__device__ float g_qkv [16384u*1536u];     // fused QKV output (row stride 1536)
__device__ float g_att [16u*512u*1024u];
__device__ float g_mh  [16u*512u*1024u];
__device__ float g_y1  [16u*512u*1024u];
__device__ float g_h1  [8192u*4096u];
__device__ float g_ff  [16u*512u*1024u];

// ---------------------------------------------------------------------------
// tf32 / cp.async helpers
// ---------------------------------------------------------------------------
__device__ __forceinline__ unsigned f2tf32(float x) {
    unsigned y;
    asm("cvt.rna.tf32.f32 %0, %1;" : "=r"(y) : "f"(x));
    return y;
}
__device__ __forceinline__ float tf32_round(float x) {
    return __uint_as_float(f2tf32(x));
}

__device__ __forceinline__ void mma_tf32(float* d, const unsigned* a, const unsigned* b) {
    asm volatile(
        "mma.sync.aligned.m16n8k8.row.col.f32.tf32.tf32.f32 "
        "{%0,%1,%2,%3}, {%4,%5,%6,%7}, {%8,%9}, {%0,%1,%2,%3};\n"
        : "+f"(d[0]), "+f"(d[1]), "+f"(d[2]), "+f"(d[3])
        : "r"(a[0]), "r"(a[1]), "r"(a[2]), "r"(a[3]), "r"(b[0]), "r"(b[1]));
}

__device__ __forceinline__ void cp16(unsigned dst, const void* src) {
    asm volatile("cp.async.cg.shared.global [%0], [%1], 16;\n" :: "r"(dst), "l"(src));
}
__device__ __forceinline__ void cp_commit() {
    asm volatile("cp.async.commit_group;\n" ::);
}
template<int N>
__device__ __forceinline__ void cp_wait() {
    asm volatile("cp.async.wait_group %0;\n" :: "n"(N));
}

// ---------------------------------------------------------------------------
// Elementwise tf32 rounding (pre-pass)
// ---------------------------------------------------------------------------
__global__ void cvt_arr(const float* __restrict__ in, float* __restrict__ out, int n)
{
    int i = blockIdx.x * blockDim.x + threadIdx.x;
    int stride = gridDim.x * blockDim.x;
    for (; i < n; i += stride) out[i] = tf32_round(in[i]);
}

// Pack Wq|Wk|Wv -> (512,1536) tf32; bias packed by first 1536 threads.
__global__ void pack_qkv(const float* __restrict__ Wq, const float* __restrict__ Wk,
                         const float* __restrict__ Wv, const float* __restrict__ bq,
                         const float* __restrict__ bk, const float* __restrict__ bv,
                         float* __restrict__ w, float* __restrict__ bias)
{
    int i = blockIdx.x * blockDim.x + threadIdx.x;     // 0 .. 512*1536-1
    int r = i / 1536, c = i % 1536;
    int seg = c >> 9, cc = c & 511;
    const float* src = (seg == 0) ? Wq : (seg == 1) ? Wk : Wv;
    w[i] = tf32_round(src[r * 512 + cc]);
    if (i < 1536) {
        int s2 = i >> 9, c2 = i & 511;
        const float* bs = (s2 == 0) ? bq : (s2 == 1) ? bk : bv;
        bias[i] = bs[c2];
    }
}

// ---------------------------------------------------------------------------
// tf32 tensor-core GEMM: 128x128 block tile, K-step 32, 256 threads,
// 8 warps in 2(M) x 4(N), warp tile 64x32 via m16n8k8. 3-stage cp.async,
// 105KB smem -> 2 blocks/SM (barrier bubbles filled by the co-resident CTA).
// Inputs pre-rounded to tf32 (raw-bit mma operands are exact).
// A pitch 36, B pitch 136: conflict-free fragment loads.
// GATHER_A folds the group reshuffle. Requires M%128==0, N%128==0, K%32==0.
// ---------------------------------------------------------------------------
#define STAGES 3
#define APITCH 36
#define BPITCH 136
#define AWORDS (128 * APITCH)          // 4608
#define BWORDS (32 * BPITCH)           // 4352
#define STAGEW (AWORDS + BWORDS)       // 8960 words
#define AB_OFF (AWORDS * 4)
#define GEMM_SMEM_BYTES (STAGES * STAGEW * 4)   // 107520

#define GEMM_ISSUE(s_) do {                                                   \
    int k0_ = (s_) << 5;                                                      \
    unsigned sb_ = sbase + (unsigned)(((s_) % STAGES) * (STAGEW * 4));        \
    _Pragma("unroll")                                                         \
    for (int i_ = 0; i_ < 4; i_++) cp16(sb_ + a_sm[i_], a_gm[i_] + k0_);      \
    _Pragma("unroll")                                                         \
    for (int i_ = 0; i_ < 4; i_++)                                            \
        cp16(sb_ + AB_OFF + b_sm[i_], b_gm[i_] + (size_t)k0_ * (size_t)N);    \
} while (0)

template<bool GATHER_A, bool RELU, bool CVT_OUT>
__global__ __launch_bounds__(256, 2)
void tgemm(const float* __restrict__ A, const float* __restrict__ Bm,
           const float* __restrict__ bias, float* __restrict__ C,
           int M, int N, int K)
{
    extern __shared__ unsigned sh[];
    const unsigned sbase = (unsigned)__cvta_generic_to_shared(sh);

    const int tid  = threadIdx.x;
    const int row0 = blockIdx.y << 7;
    const int col0 = blockIdx.x << 7;
    const int lane = tid & 31;
    const int w    = tid >> 5;
    const int wm   = w & 1;     // 0..1 (M)
    const int wn   = w >> 1;    // 0..3 (N)
    const int tig  = lane & 3;
    const int grp  = lane >> 2;

    // A copy: 4 x 16B chunks per thread (128x32 tile)
    unsigned a_sm[4];
    const float* a_gm[4];
#pragma unroll
    for (int i = 0; i < 4; i++) {
        int c  = tid + (i << 8);      // 0..1023
        int r  = c >> 3;              // row 0..127
        int kc = (c & 7) << 2;        // 0..28
        a_sm[i] = (unsigned)((r * APITCH + kc) * 4);
        int grow = row0 + r;
        if (GATHER_A) {
            int bg = grow >> 9, l = grow & 511;
            int b  = bg & 15,  g = bg >> 4;
            a_gm[i] = A + (((size_t)b * 512 + l) * 1024 + (size_t)g * 512) + kc;
        } else {
            a_gm[i] = A + (size_t)grow * (size_t)K + kc;
        }
    }
    // B copy: 4 x 16B chunks per thread (32x128 tile)
    unsigned b_sm[4];
    const float* b_gm[4];
#pragma unroll
    for (int i = 0; i < 4; i++) {
        int c  = tid + (i << 8);      // 0..1023
        int kr = c >> 5;              // 0..31
        int nc = (c & 31) << 2;       // 0..124
        b_sm[i] = (unsigned)((kr * BPITCH + nc) * 4);
        b_gm[i] = Bm + (size_t)kr * (size_t)N + col0 + nc;
    }

    float acc[4][4][4];
#pragma unroll
    for (int mi = 0; mi < 4; mi++)
#pragma unroll
        for (int ni = 0; ni < 4; ni++)
#pragma unroll
            for (int j = 0; j < 4; j++) acc[mi][ni][j] = 0.f;

    GEMM_ISSUE(0); cp_commit();
    GEMM_ISSUE(1); cp_commit();

    const int nIter = K >> 5;
    for (int it = 0; it < nIter; ++it) {
        cp_wait<1>();
        __syncthreads();

        const unsigned* Ab = sh + (it % STAGES) * STAGEW;
        const unsigned* Bb = Ab + AWORDS;
#pragma unroll
        for (int kk = 0; kk < 4; kk++) {
            unsigned af[4][4], bf[4][2];
#pragma unroll
            for (int mi = 0; mi < 4; mi++) {
                const unsigned* p = Ab + ((wm << 6) + (mi << 4) + grp) * APITCH
                                       + (kk << 3) + tig;
                af[mi][0] = p[0];
                af[mi][1] = p[8 * APITCH];
                af[mi][2] = p[4];
                af[mi][3] = p[8 * APITCH + 4];
            }
#pragma unroll
            for (int ni = 0; ni < 4; ni++) {
                const unsigned* p = Bb + ((kk << 3) + tig) * BPITCH
                                       + (wn << 5) + (ni << 3) + grp;
                bf[ni][0] = p[0];
                bf[ni][1] = p[4 * BPITCH];
            }
#pragma unroll
            for (int mi = 0; mi < 4; mi++)
#pragma unroll
                for (int ni = 0; ni < 4; ni++)
                    mma_tf32(acc[mi][ni], af[mi], bf[ni]);
        }

        int s = it + 2;
        if (s < nIter) GEMM_ISSUE(s);
        cp_commit();
    }

    // epilogue: bias (+relu) (+tf32 rounding), float2 stores
#pragma unroll
    for (int mi = 0; mi < 4; mi++) {
        int r = row0 + (wm << 6) + (mi << 4) + grp;
#pragma unroll
        for (int ni = 0; ni < 4; ni++) {
            int c = col0 + (wn << 5) + (ni << 3) + (tig << 1);
            float2 bv = *(const float2*)&bias[c];
            float v00 = acc[mi][ni][0] + bv.x;
            float v01 = acc[mi][ni][1] + bv.y;
            float v10 = acc[mi][ni][2] + bv.x;
            float v11 = acc[mi][ni][3] + bv.y;
            if (RELU) {
                v00 = fmaxf(v00, 0.f); v01 = fmaxf(v01, 0.f);
                v10 = fmaxf(v10, 0.f); v11 = fmaxf(v11, 0.f);
            }
            if (CVT_OUT) {
                v00 = tf32_round(v00); v01 = tf32_round(v01);
                v10 = tf32_round(v10); v11 = tf32_round(v11);
            }
            float2 o0; o0.x = v00; o0.y = v01;
            float2 o1; o1.x = v10; o1.y = v11;
            *(float2*)&C[(size_t)r * N + c]       = o0;
            *(float2*)&C[(size_t)(r + 8) * N + c] = o1;
        }
    }
}

// ---------------------------------------------------------------------------
// Fused attention: grid = 1024 blocks = (bg, head, row-half), 256 threads.
// Reads the fused qkv buffer (row stride 1536, col offsets q=0,k=512,v=1024).
// K/V for the head in smem (pitch 65). Each warp: 16 query rows in two
// 8-row passes. Output -> atted (B,L,H) layout, tf32-rounded.
// ---------------------------------------------------------------------------
#define ATTN_THREADS 256
#define QKV_STRIDE 1536
#define ATTN_SMEM_FLOATS (256*65*2 + 8*512 + 8*2048 + 256)
#define ATTN_SMEM_BYTES  (ATTN_SMEM_FLOATS * 4)   // 216064

__global__ __launch_bounds__(ATTN_THREADS)
void attn_kernel(const float* __restrict__ qkv, const void* __restrict__ maskp,
                 float* __restrict__ atted)
{
    extern __shared__ float sm[];
    float* Ks    = sm;                   // 256*65
    float* Vs    = Ks + 256 * 65;        // 256*65
    float* qb    = Vs + 256 * 65;        // 8 warps * 8 rows * 64
    float* pb    = qb + 8 * 512;         // 8 warps * 8 rows * 256
    float* mvals = pb + 8 * 2048;        // 256

    const int bh   = blockIdx.x >> 1;
    const int half = blockIdx.x & 1;
    const int bg   = bh >> 4;
    const int h    = bh & 15;
    const int tid  = threadIdx.x;
    const int lane = tid & 31;
    const int w    = tid >> 5;
    const int lpar  = h >> 3;
    const int cbase = (h & 7) << 6;

    // mask dtype detection (any word > 1 => byte-packed bools)
    unsigned int word = ((const unsigned int*)maskp)[tid];
    int is32 = __syncthreads_and(word <= 1u);

    const float* base = qkv + (size_t)bg * 512 * QKV_STRIDE;
    const float* qp = base;
    const float* kb = base + 512;
    const float* vb = base + 1024;

    // load K/V (float4 gmem, scalar smem stores due to pitch 65)
    for (int idx = tid; idx < 4096; idx += ATTN_THREADS) {
        int t  = idx >> 4;
        int d4 = (idx & 15) << 2;
        size_t off = (size_t)(2 * t + lpar) * QKV_STRIDE + cbase + d4;
        float4 kk4 = *(const float4*)(kb + off);
        float4 vv4 = *(const float4*)(vb + off);
        float* kd = &Ks[t * 65 + d4];
        kd[0] = kk4.x; kd[1] = kk4.y; kd[2] = kk4.z; kd[3] = kk4.w;
        float* vd = &Vs[t * 65 + d4];
        vd[0] = vv4.x; vd[1] = vv4.y; vd[2] = vv4.z; vd[3] = vv4.w;
    }
    {
        int b = bg & 15;
        int mv = is32 ? ((const int*)maskp)[b * 256 + tid]
                      : (int)((const unsigned char*)maskp)[b * 256 + tid];
        mvals[tid] = mv ? -1e9f : 0.0f;
    }
    __syncthreads();

    const float scale = 0.125f;   // 1/sqrt(64)
    float* myq = qb + w * 512;
    float* myp = pb + w * 2048;
    const int b = bg & 15;
    const int g = bg >> 4;
    const int rbase = half * 128 + w * 16;

    float mv[8];
#pragma unroll
    for (int jj = 0; jj < 8; jj++) mv[jj] = mvals[lane + 32 * jj];

    for (int pass = 0; pass < 2; pass++) {
        const int rp = rbase + pass * 8;     // first of 8 query rows

        for (int idx = lane; idx < 512; idx += 32) {
            int rr = idx >> 6, d = idx & 63;
            myq[idx] = qp[(size_t)(2 * (rp + rr) + lpar) * QKV_STRIDE + cbase + d];
        }
        __syncwarp();

        float s[8][8];
#pragma unroll
        for (int rr = 0; rr < 8; rr++)
#pragma unroll
            for (int jj = 0; jj < 8; jj++) s[rr][jj] = 0.f;

#pragma unroll 2
        for (int d = 0; d < 64; d++) {
            float kv[8];
#pragma unroll
            for (int jj = 0; jj < 8; jj++)
                kv[jj] = Ks[(lane + 32 * jj) * 65 + d];
#pragma unroll
            for (int rr = 0; rr < 8; rr++) {
                float qv = myq[rr * 64 + d];
#pragma unroll
                for (int jj = 0; jj < 8; jj++)
                    s[rr][jj] += kv[jj] * qv;
            }
        }

#pragma unroll
        for (int rr = 0; rr < 8; rr++) {
            float m = -3.0e38f;
#pragma unroll
            for (int jj = 0; jj < 8; jj++) {
                s[rr][jj] = s[rr][jj] * scale + mv[jj];
                m = fmaxf(m, s[rr][jj]);
            }
#pragma unroll
            for (int o = 16; o; o >>= 1)
                m = fmaxf(m, __shfl_xor_sync(0xffffffffu, m, o));
            float sum = 0.f;
#pragma unroll
            for (int jj = 0; jj < 8; jj++) {
                s[rr][jj] = __expf(s[rr][jj] - m);
                sum += s[rr][jj];
            }
#pragma unroll
            for (int o = 16; o; o >>= 1)
                sum += __shfl_xor_sync(0xffffffffu, sum, o);
            float inv = 1.f / sum;
#pragma unroll
            for (int jj = 0; jj < 8; jj++)
                myp[rr * 256 + lane + 32 * jj] = s[rr][jj] * inv;
        }
        __syncwarp();

        float o0[8], o1[8];
#pragma unroll
        for (int rr = 0; rr < 8; rr++) { o0[rr] = 0.f; o1[rr] = 0.f; }
#pragma unroll 4
        for (int kk = 0; kk < 256; kk++) {
            float va  = Vs[kk * 65 + lane];
            float vb2 = Vs[kk * 65 + lane + 32];
#pragma unroll
            for (int rr = 0; rr < 8; rr++) {
                float p = myp[rr * 256 + kk];
                o0[rr] += p * va;
                o1[rr] += p * vb2;
            }
        }

#pragma unroll
        for (int rr = 0; rr < 8; rr++) {
            int l = 2 * (rp + rr) + lpar;
            size_t ob = ((size_t)b * 512 + l) * 1024 + (size_t)g * 512 + cbase;
            atted[ob + lane]      = tf32_round(o0[rr]);
            atted[ob + lane + 32] = tf32_round(o1[rr]);
        }
        __syncwarp();
    }
}

// ---------------------------------------------------------------------------
// Residual-add + LayerNorm over rows of 1024. One block (256 thr) per row.
// ---------------------------------------------------------------------------
__global__ __launch_bounds__(256)
void add_ln_kernel(const float* __restrict__ res, const float* __restrict__ dlt,
                   const float* __restrict__ gamma, const float* __restrict__ beta,
                   float* __restrict__ out, int cvt_out)
{
    __shared__ float red[8];
    __shared__ float s_mean, s_inv;
    const int row = blockIdx.x;
    const int tid = threadIdx.x;
    const size_t base = (size_t)row * 1024;

    float x[4];
    float s = 0.f;
#pragma unroll
    for (int i = 0; i < 4; i++) {
        int c = tid + (i << 8);
        x[i] = res[base + c] + dlt[base + c];
        s += x[i];
    }
#pragma unroll
    for (int o = 16; o; o >>= 1) s += __shfl_xor_sync(0xffffffffu, s, o);
    if ((tid & 31) == 0) red[tid >> 5] = s;
    __syncthreads();
    if (tid < 32) {
        float t = (tid < 8) ? red[tid] : 0.f;
#pragma unroll
        for (int o = 4; o; o >>= 1) t += __shfl_xor_sync(0xffffffffu, t, o);
        if (tid == 0) s_mean = t * (1.f / 1024.f);
    }
    __syncthreads();
    const float mean = s_mean;

    float vs = 0.f;
#pragma unroll
    for (int i = 0; i < 4; i++) { float d = x[i] - mean; vs += d * d; }
#pragma unroll
    for (int o = 16; o; o >>= 1) vs += __shfl_xor_sync(0xffffffffu, vs, o);
    if ((tid & 31) == 0) red[tid >> 5] = vs;
    __syncthreads();
    if (tid < 32) {
        float t = (tid < 8) ? red[tid] : 0.f;
#pragma unroll
        for (int o = 4; o; o >>= 1) t += __shfl_xor_sync(0xffffffffu, t, o);
        if (tid == 0) s_inv = rsqrtf(t * (1.f / 1024.f) + 1e-6f);
    }
    __syncthreads();
    const float inv = s_inv;

#pragma unroll
    for (int i = 0; i < 4; i++) {
        int c = tid + (i << 8);
        float v = (x[i] - mean) * inv * gamma[c] + beta[c];
        out[base + c] = cvt_out ? tf32_round(v) : v;
    }
}

// ---------------------------------------------------------------------------
// Launch
// ---------------------------------------------------------------------------
extern "C" void kernel_launch(void* const* d_in, const int* in_sizes, int n_in,
                              void* d_out, int out_size)
{
    const float* y   = (const float*)d_in[0];
    const void*  msk = d_in[1];
    const float* Wv  = (const float*)d_in[2];
    const float* bv  = (const float*)d_in[3];
    const float* Wk  = (const float*)d_in[4];
    const float* bk  = (const float*)d_in[5];
    const float* Wq  = (const float*)d_in[6];
    const float* bq  = (const float*)d_in[7];
    const float* Wm  = (const float*)d_in[8];
    const float* bm  = (const float*)d_in[9];
    const float* W1  = (const float*)d_in[10];
    const float* b1  = (const float*)d_in[11];
    const float* W2  = (const float*)d_in[12];
    const float* b2  = (const float*)d_in[13];
    const float* g1  = (const float*)d_in[14];
    const float* be1 = (const float*)d_in[15];
    const float* g2  = (const float*)d_in[16];
    const float* be2 = (const float*)d_in[17];
    float* out = (float*)d_out;

    float *yc, *wqkv, *bqkv, *wm, *w1, *w2;
    float *qkv, *att, *mh, *y1, *h1, *ff;
    cudaGetSymbolAddress((void**)&yc,   g_yc);
    cudaGetSymbolAddress((void**)&wqkv, g_wqkv);
    cudaGetSymbolAddress((void**)&bqkv, g_bqkv);
    cudaGetSymbolAddress((void**)&wm,   g_wm);
    cudaGetSymbolAddress((void**)&w1,   g_w1);
    cudaGetSymbolAddress((void**)&w2,   g_w2);
    cudaGetSymbolAddress((void**)&qkv,  g_qkv);
    cudaGetSymbolAddress((void**)&att,  g_att);
    cudaGetSymbolAddress((void**)&mh,   g_mh);
    cudaGetSymbolAddress((void**)&y1,   g_y1);
    cudaGetSymbolAddress((void**)&h1,   g_h1);
    cudaGetSymbolAddress((void**)&ff,   g_ff);

    cudaFuncSetAttribute(attn_kernel,
                         cudaFuncAttributeMaxDynamicSharedMemorySize, ATTN_SMEM_BYTES);
    cudaFuncSetAttribute(tgemm<true,  false, true >,
                         cudaFuncAttributeMaxDynamicSharedMemorySize, GEMM_SMEM_BYTES);
    cudaFuncSetAttribute(tgemm<false, false, false>,
                         cudaFuncAttributeMaxDynamicSharedMemorySize, GEMM_SMEM_BYTES);
    cudaFuncSetAttribute(tgemm<false, true,  true >,
                         cudaFuncAttributeMaxDynamicSharedMemorySize, GEMM_SMEM_BYTES);

    dim3 blk(256);

    // Pre-round GEMM inputs to tf32 (rna); pack QKV weights/bias
    cvt_arr<<<2048, 512>>>(y,  yc, 16*512*1024);
    pack_qkv<<<1536, 512>>>(Wq, Wk, Wv, bq, bk, bv, wqkv, bqkv);
    cvt_arr<<<1024, 512>>>(Wm, wm, 1024*1024);
    cvt_arr<<<2048, 512>>>(W1, w1, 1024*4096);
    cvt_arr<<<1024, 512>>>(W2, w2, 2048*512);

    // Fused QKV: (16384,1536) = gather(yc) @ wqkv (512,1536) + bqkv
    tgemm<true,  false, true ><<<dim3(12, 128), blk, GEMM_SMEM_BYTES>>>(yc, wqkv, bqkv, qkv, 16384, 1536, 512);

    // Attention (fused scores+softmax+ctx) -> atted layout, tf32-rounded
    attn_kernel<<<1024, ATTN_THREADS, ATTN_SMEM_BYTES>>>(qkv, msk, att);

    // Merge: (8192,1024) @ wm (1024,1024) + bm
    tgemm<false, false, false><<<dim3(8, 64), blk, GEMM_SMEM_BYTES>>>(att, wm, bm, mh, 8192, 1024, 1024);

    // y1 = LN(y + merge), tf32-rounded (feeds FFN1)
    add_ln_kernel<<<8192, blk>>>(y, mh, g1, be1, y1, 1);

    // FFN1: (8192,1024) @ w1 (1024,4096) + b1, relu, tf32-rounded
    tgemm<false, true,  true ><<<dim3(32, 64), blk, GEMM_SMEM_BYTES>>>(y1, w1, b1, h1, 8192, 4096, 1024);

    // FFN2 (grouped == contiguous reinterpret): (16384,2048) @ w2 (2048,512) + b2
    tgemm<false, false, false><<<dim3(4, 128), blk, GEMM_SMEM_BYTES>>>(h1, w2, b2, ff, 16384, 512, 2048);

    // out = LN(y1 + ff), full fp32
    add_ln_kernel<<<8192, blk>>>(y1, ff, g2, be2, out, 0);
}

// round 6
// speedup vs baseline: 1.4348x; 1.4348x over previous
#include <cuda_runtime.h>
#include <cuda_fp16.h>
#include <math.h>
#include <stdint.h>

// ---------------------------------------------------------------------------
// Problem constants: B=16, L=512, H=1024, G=2, NH=16, DH=64, FF=4096,
//                    DM=512, LG=256
// ---------------------------------------------------------------------------

// Scratch (device globals; allocation inside kernel_launch is forbidden)
__device__ __half g_yh   [16u*512u*1024u];   // half copy of y (GEMM A input)
__device__ __half g_wqkvT[1536u*512u];       // (N,K) transposed packed Wq|Wk|Wv
__device__ float  g_bqkv [1536u];
__device__ __half g_wmT  [1024u*1024u];      // (N,K)
__device__ __half g_w1T  [4096u*1024u];
__device__ __half g_w2T  [512u*2048u];
__device__ __half g_qkv  [16384u*1536u];     // fused QKV output (row stride 1536)
__device__ __half g_att  [16u*512u*1024u];   // attention output (GEMM A input)
__device__ float  g_mh   [16u*512u*1024u];
__device__ float  g_y1   [16u*512u*1024u];   // LN1 out fp32 (residual)
__device__ __half g_y1h  [16u*512u*1024u];   // LN1 out half (FFN1 A input)
__device__ __half g_h1   [8192u*4096u];      // FFN hidden (relu, half)
__device__ float  g_ff   [16u*512u*1024u];

// ---------------------------------------------------------------------------
// Helpers
// ---------------------------------------------------------------------------
__device__ __forceinline__ void mma_f16(float* d, const unsigned* a, const unsigned* b) {
    asm volatile(
        "mma.sync.aligned.m16n8k16.row.col.f32.f16.f16.f32 "
        "{%0,%1,%2,%3}, {%4,%5,%6,%7}, {%8,%9}, {%0,%1,%2,%3};\n"
        : "+f"(d[0]), "+f"(d[1]), "+f"(d[2]), "+f"(d[3])
        : "r"(a[0]), "r"(a[1]), "r"(a[2]), "r"(a[3]), "r"(b[0]), "r"(b[1]));
}

__device__ __forceinline__ void cp16(unsigned dst, const void* src) {
    asm volatile("cp.async.cg.shared.global [%0], [%1], 16;\n" :: "r"(dst), "l"(src));
}
__device__ __forceinline__ void cp_commit() {
    asm volatile("cp.async.commit_group;\n" ::);
}
template<int N>
__device__ __forceinline__ void cp_wait() {
    asm volatile("cp.async.wait_group %0;\n" :: "n"(N));
}

// ---------------------------------------------------------------------------
// Pre-passes
// ---------------------------------------------------------------------------
__global__ void cvt_half(const float* __restrict__ in, __half* __restrict__ out, int n)
{
    int i = blockIdx.x * blockDim.x + threadIdx.x;
    int stride = gridDim.x * blockDim.x;
    for (; i < n; i += stride) out[i] = __float2half(in[i]);
}

// Tiled transpose + half convert: in[K,N] fp32 -> out[N,K] half
__global__ void transp(const float* __restrict__ in, __half* __restrict__ out,
                       int K, int N)
{
    __shared__ float t[32][33];
    int nb = blockIdx.x << 5, kb = blockIdx.y << 5;
    int tx = threadIdx.x, ty = threadIdx.y;
#pragma unroll
    for (int i = 0; i < 32; i += 8)
        t[ty + i][tx] = in[(size_t)(kb + ty + i) * N + nb + tx];
    __syncthreads();
#pragma unroll
    for (int i = 0; i < 32; i += 8)
        out[(size_t)(nb + ty + i) * K + kb + tx] = __float2half(t[tx][ty + i]);
}

// Transpose+convert+pack Wq|Wk|Wv (each 512x512) -> out (1536, 512) half
__global__ void transp_qkv(const float* __restrict__ Wq, const float* __restrict__ Wk,
                           const float* __restrict__ Wv, __half* __restrict__ out)
{
    __shared__ float t[32][33];
    int nb = blockIdx.x << 5, kb = blockIdx.y << 5;
    const float* src = (nb < 512) ? Wq : (nb < 1024) ? Wk : Wv;
    int nloc = nb & 511;
    int tx = threadIdx.x, ty = threadIdx.y;
#pragma unroll
    for (int i = 0; i < 32; i += 8)
        t[ty + i][tx] = src[(size_t)(kb + ty + i) * 512 + nloc + tx];
    __syncthreads();
#pragma unroll
    for (int i = 0; i < 32; i += 8)
        out[(size_t)(nb + ty + i) * 512 + kb + tx] = __float2half(t[tx][ty + i]);
}

__global__ void pack_bias(const float* __restrict__ bq, const float* __restrict__ bk,
                          const float* __restrict__ bv, float* __restrict__ bias)
{
    int i = blockIdx.x * blockDim.x + threadIdx.x;
    if (i < 1536) {
        int s = i >> 9, c = i & 511;
        const float* bs = (s == 0) ? bq : (s == 1) ? bk : bv;
        bias[i] = bs[c];
    }
}

// ---------------------------------------------------------------------------
// fp16 tensor-core GEMM (mma.sync m16n8k16, fp32 accumulate).
// Block tile 128x128, K-step 32 (halves), 256 threads, 8 warps 2(M)x4(N),
// warp tile 64x32. 3-stage cp.async pipeline, 60KB smem -> 2 CTAs/SM.
// A (M,K) half row-major (optionally gathered), BT (N,K) half (pre-transposed
// weight -> B col-major fragments are k-contiguous). Smem pitch 40 halves
// (20 words): fragment loads are bank-conflict-free (grp*20+tig covers all
// 32 banks). GATHER_A folds the group reshuffle on y.
// Requires M%128==0, N%128==0, K%32==0.
// ---------------------------------------------------------------------------
#define STAGES 3
#define ROW_BYTES 80                  // 40 halves/row (32 data + 8 pad)
#define A_BYTES (128 * ROW_BYTES)     // 10240
#define STAGE_BYTES (2 * A_BYTES)     // 20480
#define GEMM_SMEM_BYTES (STAGES * STAGE_BYTES)  // 61440

#define GEMM_ISSUE(s_) do {                                                   \
    int ko_ = (s_) << 5;                                                      \
    unsigned sb_ = sbase + (unsigned)(((s_) % STAGES) * STAGE_BYTES);         \
    _Pragma("unroll")                                                         \
    for (int i_ = 0; i_ < 2; i_++) cp16(sb_ + a_sm[i_], a_gm[i_] + ko_);      \
    _Pragma("unroll")                                                         \
    for (int i_ = 0; i_ < 2; i_++)                                            \
        cp16(sb_ + A_BYTES + b_sm[i_], b_gm[i_] + ko_);                       \
} while (0)

template<bool GATHER_A, bool RELU, bool OUT_HALF>
__global__ __launch_bounds__(256, 2)
void hgemm(const __half* __restrict__ A, const __half* __restrict__ BT,
           const float* __restrict__ bias, void* __restrict__ Cv,
           int M, int N, int K)
{
    extern __shared__ unsigned char dsm[];
    const unsigned sbase = (unsigned)__cvta_generic_to_shared(dsm);

    const int tid  = threadIdx.x;
    const int row0 = blockIdx.y << 7;
    const int col0 = blockIdx.x << 7;
    const int lane = tid & 31;
    const int w    = tid >> 5;
    const int wm   = w & 1;     // 0..1 (M)
    const int wn   = w >> 1;    // 0..3 (N)
    const int tig  = lane & 3;
    const int grp  = lane >> 2;

    // copy descriptors: 2 x 16B chunks per thread for A and for B
    unsigned a_sm[2], b_sm[2];
    const __half* a_gm[2];
    const __half* b_gm[2];
#pragma unroll
    for (int i = 0; i < 2; i++) {
        int ci = tid + (i << 8);        // 0..511
        int r  = ci >> 2;               // row 0..127
        int kc = (ci & 3) << 3;         // k offset in halves: 0,8,16,24
        a_sm[i] = (unsigned)(r * ROW_BYTES + (kc << 1));
        b_sm[i] = a_sm[i];
        int grow = row0 + r;
        if (GATHER_A) {
            int bg = grow >> 9, l = grow & 511;
            int b  = bg & 15,  g = bg >> 4;
            a_gm[i] = A + (((size_t)b * 512 + l) * 1024 + (size_t)g * 512) + kc;
        } else {
            a_gm[i] = A + (size_t)grow * (size_t)K + kc;
        }
        b_gm[i] = BT + (size_t)(col0 + r) * (size_t)K + kc;
    }

    float acc[4][4][4];
#pragma unroll
    for (int mi = 0; mi < 4; mi++)
#pragma unroll
        for (int ni = 0; ni < 4; ni++)
#pragma unroll
            for (int j = 0; j < 4; j++) acc[mi][ni][j] = 0.f;

    GEMM_ISSUE(0); cp_commit();
    GEMM_ISSUE(1); cp_commit();

    const int nIter = K >> 5;
    for (int it = 0; it < nIter; ++it) {
        cp_wait<1>();
        __syncthreads();

        const unsigned* Aw = (const unsigned*)(dsm + (it % STAGES) * STAGE_BYTES);
        const unsigned* Bw = (const unsigned*)(dsm + (it % STAGES) * STAGE_BYTES + A_BYTES);
#pragma unroll
        for (int ks = 0; ks < 2; ks++) {
            unsigned af[4][4], bf[4][2];
#pragma unroll
            for (int mi = 0; mi < 4; mi++) {
                const unsigned* p = Aw + ((wm << 6) + (mi << 4) + grp) * 20
                                       + (ks << 3) + tig;
                af[mi][0] = p[0];
                af[mi][1] = p[160];      // +8 rows
                af[mi][2] = p[4];        // +8 k (halves)
                af[mi][3] = p[164];
            }
#pragma unroll
            for (int ni = 0; ni < 4; ni++) {
                const unsigned* p = Bw + ((wn << 5) + (ni << 3) + grp) * 20
                                       + (ks << 3) + tig;
                bf[ni][0] = p[0];
                bf[ni][1] = p[4];
            }
#pragma unroll
            for (int mi = 0; mi < 4; mi++)
#pragma unroll
                for (int ni = 0; ni < 4; ni++)
                    mma_f16(acc[mi][ni], af[mi], bf[ni]);
        }

        int s = it + 2;
        if (s < nIter) GEMM_ISSUE(s);
        cp_commit();
    }

    // epilogue: bias (+relu), half2 or float2 stores
#pragma unroll
    for (int mi = 0; mi < 4; mi++) {
        int r = row0 + (wm << 6) + (mi << 4) + grp;
#pragma unroll
        for (int ni = 0; ni < 4; ni++) {
            int c = col0 + (wn << 5) + (ni << 3) + (tig << 1);
            float2 bv = *(const float2*)&bias[c];
            float v00 = acc[mi][ni][0] + bv.x;
            float v01 = acc[mi][ni][1] + bv.y;
            float v10 = acc[mi][ni][2] + bv.x;
            float v11 = acc[mi][ni][3] + bv.y;
            if (RELU) {
                v00 = fmaxf(v00, 0.f); v01 = fmaxf(v01, 0.f);
                v10 = fmaxf(v10, 0.f); v11 = fmaxf(v11, 0.f);
            }
            if (OUT_HALF) {
                __half* Ch = (__half*)Cv;
                *(__half2*)&Ch[(size_t)r * N + c]       = __floats2half2_rn(v00, v01);
                *(__half2*)&Ch[(size_t)(r + 8) * N + c] = __floats2half2_rn(v10, v11);
            } else {
                float* Cf = (float*)Cv;
                float2 o0; o0.x = v00; o0.y = v01;
                float2 o1; o1.x = v10; o1.y = v11;
                *(float2*)&Cf[(size_t)r * N + c]       = o0;
                *(float2*)&Cf[(size_t)(r + 8) * N + c] = o1;
            }
        }
    }
}

// ---------------------------------------------------------------------------
// Fused attention: grid = 1024 blocks = (bg, head, row-half), 256 threads.
// Reads the fused qkv half buffer (row stride 1536, offsets q=0,k=512,v=1024),
// converts to fp32 in smem (K/V pitch 65). Each warp: 16 query rows in two
// 8-row passes. Output -> att (B,L,H) half layout.
// ---------------------------------------------------------------------------
#define ATTN_THREADS 256
#define QKV_STRIDE 1536
#define ATTN_SMEM_FLOATS (256*65*2 + 8*512 + 8*2048 + 256)
#define ATTN_SMEM_BYTES  (ATTN_SMEM_FLOATS * 4)   // 216064

__global__ __launch_bounds__(ATTN_THREADS)
void attn_kernel(const __half* __restrict__ qkv, const void* __restrict__ maskp,
                 __half* __restrict__ atted)
{
    extern __shared__ float sm[];
    float* Ks    = sm;
    float* Vs    = Ks + 256 * 65;
    float* qb    = Vs + 256 * 65;
    float* pb    = qb + 8 * 512;
    float* mvals = pb + 8 * 2048;

    const int bh   = blockIdx.x >> 1;
    const int half = blockIdx.x & 1;
    const int bg   = bh >> 4;
    const int h    = bh & 15;
    const int tid  = threadIdx.x;
    const int lane = tid & 31;
    const int w    = tid >> 5;
    const int lpar  = h >> 3;
    const int cbase = (h & 7) << 6;

    // mask dtype detection (any word > 1 => byte-packed bools)
    unsigned int word = ((const unsigned int*)maskp)[tid];
    int is32 = __syncthreads_and(word <= 1u);

    const __half* base = qkv + (size_t)bg * 512 * QKV_STRIDE;
    const __half* qp = base;
    const __half* kb = base + 512;
    const __half* vb = base + 1024;

    // load K/V: 16B = 8 halves per chunk, convert to fp32 into pitch-65 smem
    for (int idx = tid; idx < 2048; idx += ATTN_THREADS) {
        int t  = idx >> 3;             // 0..255
        int d8 = (idx & 7) << 3;       // 0..56
        size_t off = (size_t)(2 * t + lpar) * QKV_STRIDE + cbase + d8;
        uint4 kraw = *(const uint4*)(kb + off);
        uint4 vraw = *(const uint4*)(vb + off);
        const __half2* kh = (const __half2*)&kraw;
        const __half2* vh = (const __half2*)&vraw;
        float* kd = &Ks[t * 65 + d8];
        float* vd = &Vs[t * 65 + d8];
#pragma unroll
        for (int j = 0; j < 4; j++) {
            float2 kf = __half22float2(kh[j]);
            float2 vf = __half22float2(vh[j]);
            kd[2*j] = kf.x; kd[2*j+1] = kf.y;
            vd[2*j] = vf.x; vd[2*j+1] = vf.y;
        }
    }
    {
        int b = bg & 15;
        int mv = is32 ? ((const int*)maskp)[b * 256 + tid]
                      : (int)((const unsigned char*)maskp)[b * 256 + tid];
        mvals[tid] = mv ? -1e9f : 0.0f;
    }
    __syncthreads();

    const float scale = 0.125f;
    float* myq = qb + w * 512;
    float* myp = pb + w * 2048;
    const int b = bg & 15;
    const int g = bg >> 4;
    const int rbase = half * 128 + w * 16;

    float mv[8];
#pragma unroll
    for (int jj = 0; jj < 8; jj++) mv[jj] = mvals[lane + 32 * jj];

    for (int pass = 0; pass < 2; pass++) {
        const int rp = rbase + pass * 8;

        for (int idx = lane; idx < 512; idx += 32) {
            int rr = idx >> 6, d = idx & 63;
            myq[idx] = __half2float(
                qp[(size_t)(2 * (rp + rr) + lpar) * QKV_STRIDE + cbase + d]);
        }
        __syncwarp();

        float s[8][8];
#pragma unroll
        for (int rr = 0; rr < 8; rr++)
#pragma unroll
            for (int jj = 0; jj < 8; jj++) s[rr][jj] = 0.f;

#pragma unroll 2
        for (int d = 0; d < 64; d++) {
            float kv[8];
#pragma unroll
            for (int jj = 0; jj < 8; jj++)
                kv[jj] = Ks[(lane + 32 * jj) * 65 + d];
#pragma unroll
            for (int rr = 0; rr < 8; rr++) {
                float qv = myq[rr * 64 + d];
#pragma unroll
                for (int jj = 0; jj < 8; jj++)
                    s[rr][jj] += kv[jj] * qv;
            }
        }

#pragma unroll
        for (int rr = 0; rr < 8; rr++) {
            float m = -3.0e38f;
#pragma unroll
            for (int jj = 0; jj < 8; jj++) {
                s[rr][jj] = s[rr][jj] * scale + mv[jj];
                m = fmaxf(m, s[rr][jj]);
            }
#pragma unroll
            for (int o = 16; o; o >>= 1)
                m = fmaxf(m, __shfl_xor_sync(0xffffffffu, m, o));
            float sum = 0.f;
#pragma unroll
            for (int jj = 0; jj < 8; jj++) {
                s[rr][jj] = __expf(s[rr][jj] - m);
                sum += s[rr][jj];
            }
#pragma unroll
            for (int o = 16; o; o >>= 1)
                sum += __shfl_xor_sync(0xffffffffu, sum, o);
            float inv = 1.f / sum;
#pragma unroll
            for (int jj = 0; jj < 8; jj++)
                myp[rr * 256 + lane + 32 * jj] = s[rr][jj] * inv;
        }
        __syncwarp();

        float o0[8], o1[8];
#pragma unroll
        for (int rr = 0; rr < 8; rr++) { o0[rr] = 0.f; o1[rr] = 0.f; }
#pragma unroll 4
        for (int kk = 0; kk < 256; kk++) {
            float va  = Vs[kk * 65 + lane];
            float vb2 = Vs[kk * 65 + lane + 32];
#pragma unroll
            for (int rr = 0; rr < 8; rr++) {
                float p = myp[rr * 256 + kk];
                o0[rr] += p * va;
                o1[rr] += p * vb2;
            }
        }

#pragma unroll
        for (int rr = 0; rr < 8; rr++) {
            int l = 2 * (rp + rr) + lpar;
            size_t ob = ((size_t)b * 512 + l) * 1024 + (size_t)g * 512 + cbase;
            atted[ob + lane]      = __float2half(o0[rr]);
            atted[ob + lane + 32] = __float2half(o1[rr]);
        }
        __syncwarp();
    }
}

// ---------------------------------------------------------------------------
// Residual-add + LayerNorm over rows of 1024. One block (256 thr) per row.
// outh (optional): also write half copy (for feeding the next GEMM).
// ---------------------------------------------------------------------------
__global__ __launch_bounds__(256)
void add_ln_kernel(const float* __restrict__ res, const float* __restrict__ dlt,
                   const float* __restrict__ gamma, const float* __restrict__ beta,
                   float* __restrict__ out, __half* __restrict__ outh)
{
    __shared__ float red[8];
    __shared__ float s_mean, s_inv;
    const int row = blockIdx.x;
    const int tid = threadIdx.x;
    const size_t base = (size_t)row * 1024;

    float x[4];
    float s = 0.f;
#pragma unroll
    for (int i = 0; i < 4; i++) {
        int c = tid + (i << 8);
        x[i] = res[base + c] + dlt[base + c];
        s += x[i];
    }
#pragma unroll
    for (int o = 16; o; o >>= 1) s += __shfl_xor_sync(0xffffffffu, s, o);
    if ((tid & 31) == 0) red[tid >> 5] = s;
    __syncthreads();
    if (tid < 32) {
        float t = (tid < 8) ? red[tid] : 0.f;
#pragma unroll
        for (int o = 4; o; o >>= 1) t += __shfl_xor_sync(0xffffffffu, t, o);
        if (tid == 0) s_mean = t * (1.f / 1024.f);
    }
    __syncthreads();
    const float mean = s_mean;

    float vs = 0.f;
#pragma unroll
    for (int i = 0; i < 4; i++) { float d = x[i] - mean; vs += d * d; }
#pragma unroll
    for (int o = 16; o; o >>= 1) vs += __shfl_xor_sync(0xffffffffu, vs, o);
    if ((tid & 31) == 0) red[tid >> 5] = vs;
    __syncthreads();
    if (tid < 32) {
        float t = (tid < 8) ? red[tid] : 0.f;
#pragma unroll
        for (int o = 4; o; o >>= 1) t += __shfl_xor_sync(0xffffffffu, t, o);
        if (tid == 0) s_inv = rsqrtf(t * (1.f / 1024.f) + 1e-6f);
    }
    __syncthreads();
    const float inv = s_inv;

#pragma unroll
    for (int i = 0; i < 4; i++) {
        int c = tid + (i << 8);
        float v = (x[i] - mean) * inv * gamma[c] + beta[c];
        out[base + c] = v;
        if (outh) outh[base + c] = __float2half(v);
    }
}

// ---------------------------------------------------------------------------
// Launch
// ---------------------------------------------------------------------------
extern "C" void kernel_launch(void* const* d_in, const int* in_sizes, int n_in,
                              void* d_out, int out_size)
{
    const float* y   = (const float*)d_in[0];
    const void*  msk = d_in[1];
    const float* Wv  = (const float*)d_in[2];
    const float* bv  = (const float*)d_in[3];
    const float* Wk  = (const float*)d_in[4];
    const float* bk  = (const float*)d_in[5];
    const float* Wq  = (const float*)d_in[6];
    const float* bq  = (const float*)d_in[7];
    const float* Wm  = (const float*)d_in[8];
    const float* bm  = (const float*)d_in[9];
    const float* W1  = (const float*)d_in[10];
    const float* b1  = (const float*)d_in[11];
    const float* W2  = (const float*)d_in[12];
    const float* b2  = (const float*)d_in[13];
    const float* g1  = (const float*)d_in[14];
    const float* be1 = (const float*)d_in[15];
    const float* g2  = (const float*)d_in[16];
    const float* be2 = (const float*)d_in[17];
    float* out = (float*)d_out;

    __half *yh, *wqkvT, *wmT, *w1T, *w2T, *qkv, *att, *y1h, *h1;
    float *bqkv, *mh, *y1, *ff;
    cudaGetSymbolAddress((void**)&yh,    g_yh);
    cudaGetSymbolAddress((void**)&wqkvT, g_wqkvT);
    cudaGetSymbolAddress((void**)&bqkv,  g_bqkv);
    cudaGetSymbolAddress((void**)&wmT,   g_wmT);
    cudaGetSymbolAddress((void**)&w1T,   g_w1T);
    cudaGetSymbolAddress((void**)&w2T,   g_w2T);
    cudaGetSymbolAddress((void**)&qkv,   g_qkv);
    cudaGetSymbolAddress((void**)&att,   g_att);
    cudaGetSymbolAddress((void**)&mh,    g_mh);
    cudaGetSymbolAddress((void**)&y1,    g_y1);
    cudaGetSymbolAddress((void**)&y1h,   g_y1h);
    cudaGetSymbolAddress((void**)&h1,    g_h1);
    cudaGetSymbolAddress((void**)&ff,    g_ff);

    cudaFuncSetAttribute(attn_kernel,
                         cudaFuncAttributeMaxDynamicSharedMemorySize, ATTN_SMEM_BYTES);
    cudaFuncSetAttribute(hgemm<true,  false, true >,
                         cudaFuncAttributeMaxDynamicSharedMemorySize, GEMM_SMEM_BYTES);
    cudaFuncSetAttribute(hgemm<false, false, false>,
                         cudaFuncAttributeMaxDynamicSharedMemorySize, GEMM_SMEM_BYTES);
    cudaFuncSetAttribute(hgemm<false, true,  true >,
                         cudaFuncAttributeMaxDynamicSharedMemorySize, GEMM_SMEM_BYTES);
    cudaFuncSetAttribute(hgemm<false, false, true >,
                         cudaFuncAttributeMaxDynamicSharedMemorySize, GEMM_SMEM_BYTES);

    dim3 blk(256);
    dim3 tblk(32, 8);

    // Pre-passes: y -> half; weights -> transposed (N,K) half; pack qkv bias
    cvt_half<<<2048, 512>>>(y, yh, 16*512*1024);
    transp_qkv<<<dim3(48, 16),  tblk>>>(Wq, Wk, Wv, wqkvT);
    pack_bias<<<3, 512>>>(bq, bk, bv, bqkv);
    transp<<<dim3(32, 32),  tblk>>>(Wm, wmT, 1024, 1024);
    transp<<<dim3(128, 32), tblk>>>(W1, w1T, 1024, 4096);
    transp<<<dim3(16, 64),  tblk>>>(W2, w2T, 2048, 512);

    // Fused QKV: (16384,1536) = gather(yh) @ Wqkv + bqkv  -> half
    hgemm<true,  false, true ><<<dim3(12, 128), blk, GEMM_SMEM_BYTES>>>(yh, wqkvT, bqkv, qkv, 16384, 1536, 512);

    // Attention -> att (half, B,L,H layout)
    attn_kernel<<<1024, ATTN_THREADS, ATTN_SMEM_BYTES>>>(qkv, msk, att);

    // Merge: (8192,1024) @ Wm + bm -> fp32
    hgemm<false, false, false><<<dim3(8, 64), blk, GEMM_SMEM_BYTES>>>(att, wmT, bm, mh, 8192, 1024, 1024);

    // y1 = LN(y + merge): fp32 (residual) + half (FFN1 input)
    add_ln_kernel<<<8192, blk>>>(y, mh, g1, be1, y1, y1h);

    // FFN1: (8192,1024) @ W1 + b1, relu -> half
    hgemm<false, true,  true ><<<dim3(32, 64), blk, GEMM_SMEM_BYTES>>>(y1h, w1T, b1, h1, 8192, 4096, 1024);

    // FFN2 (grouped == contiguous reinterpret): (16384,2048) @ W2 + b2 -> fp32
    hgemm<false, false, false><<<dim3(4, 128), blk, GEMM_SMEM_BYTES>>>(h1, w2T, b2, ff, 16384, 512, 2048);

    // out = LN(y1 + ff), full fp32
    add_ln_kernel<<<8192, blk>>>(y1, ff, g2, be2, out, (__half*)0);
}

// round 7
// speedup vs baseline: 1.9939x; 1.3897x over previous
#include <cuda_runtime.h>
#include <cuda_fp16.h>
#include <math.h>
#include <stdint.h>

// ---------------------------------------------------------------------------
// Problem constants: B=16, L=512, H=1024, G=2, NH=16, DH=64, FF=4096,
//                    DM=512, LG=256
// ---------------------------------------------------------------------------

// Scratch (device globals; allocation inside kernel_launch is forbidden)
__device__ __half g_yh   [16u*512u*1024u];   // half copy of y (GEMM A input)
__device__ __half g_wqkvT[1536u*512u];       // (N,K) transposed packed Wq|Wk|Wv
__device__ float  g_bqkv [1536u];
__device__ __half g_wmT  [1024u*1024u];      // (N,K)
__device__ __half g_w1T  [4096u*1024u];
__device__ __half g_w2T  [512u*2048u];
__device__ __half g_qkv  [16384u*1536u];     // fused QKV output (row stride 1536)
__device__ __half g_att  [16u*512u*1024u];   // attention output (GEMM A input)
__device__ float  g_mh   [16u*512u*1024u];
__device__ float  g_y1   [16u*512u*1024u];   // LN1 out fp32 (residual)
__device__ __half g_y1h  [16u*512u*1024u];   // LN1 out half (FFN1 A input)
__device__ __half g_h1   [8192u*4096u];      // FFN hidden (relu, half)
__device__ float  g_ff   [16u*512u*1024u];

// ---------------------------------------------------------------------------
// Helpers
// ---------------------------------------------------------------------------
__device__ __forceinline__ void mma_f16(float* d, const unsigned* a, const unsigned* b) {
    asm volatile(
        "mma.sync.aligned.m16n8k16.row.col.f32.f16.f16.f32 "
        "{%0,%1,%2,%3}, {%4,%5,%6,%7}, {%8,%9}, {%0,%1,%2,%3};\n"
        : "+f"(d[0]), "+f"(d[1]), "+f"(d[2]), "+f"(d[3])
        : "r"(a[0]), "r"(a[1]), "r"(a[2]), "r"(a[3]), "r"(b[0]), "r"(b[1]));
}

__device__ __forceinline__ void ldsm_x4(unsigned* r, unsigned a) {
    asm volatile("ldmatrix.sync.aligned.m8n8.x4.shared.b16 {%0,%1,%2,%3}, [%4];"
        : "=r"(r[0]), "=r"(r[1]), "=r"(r[2]), "=r"(r[3]) : "r"(a));
}
__device__ __forceinline__ void ldsm_x4_t(unsigned* r, unsigned a) {
    asm volatile("ldmatrix.sync.aligned.m8n8.x4.trans.shared.b16 {%0,%1,%2,%3}, [%4];"
        : "=r"(r[0]), "=r"(r[1]), "=r"(r[2]), "=r"(r[3]) : "r"(a));
}

__device__ __forceinline__ void cp16(unsigned dst, const void* src) {
    asm volatile("cp.async.cg.shared.global [%0], [%1], 16;\n" :: "r"(dst), "l"(src));
}
__device__ __forceinline__ void cp_commit() {
    asm volatile("cp.async.commit_group;\n" ::);
}
template<int N>
__device__ __forceinline__ void cp_wait() {
    asm volatile("cp.async.wait_group %0;\n" :: "n"(N));
}

// ---------------------------------------------------------------------------
// Pre-passes
// ---------------------------------------------------------------------------
__global__ void cvt_half(const float* __restrict__ in, __half* __restrict__ out, int n)
{
    int i = blockIdx.x * blockDim.x + threadIdx.x;
    int stride = gridDim.x * blockDim.x;
    for (; i < n; i += stride) out[i] = __float2half(in[i]);
}

// Tiled transpose + half convert: in[K,N] fp32 -> out[N,K] half
__global__ void transp(const float* __restrict__ in, __half* __restrict__ out,
                       int K, int N)
{
    __shared__ float t[32][33];
    int nb = blockIdx.x << 5, kb = blockIdx.y << 5;
    int tx = threadIdx.x, ty = threadIdx.y;
#pragma unroll
    for (int i = 0; i < 32; i += 8)
        t[ty + i][tx] = in[(size_t)(kb + ty + i) * N + nb + tx];
    __syncthreads();
#pragma unroll
    for (int i = 0; i < 32; i += 8)
        out[(size_t)(nb + ty + i) * K + kb + tx] = __float2half(t[tx][ty + i]);
}

// Transpose+convert+pack Wq|Wk|Wv (each 512x512) -> out (1536, 512) half
__global__ void transp_qkv(const float* __restrict__ Wq, const float* __restrict__ Wk,
                           const float* __restrict__ Wv, __half* __restrict__ out)
{
    __shared__ float t[32][33];
    int nb = blockIdx.x << 5, kb = blockIdx.y << 5;
    const float* src = (nb < 512) ? Wq : (nb < 1024) ? Wk : Wv;
    int nloc = nb & 511;
    int tx = threadIdx.x, ty = threadIdx.y;
#pragma unroll
    for (int i = 0; i < 32; i += 8)
        t[ty + i][tx] = src[(size_t)(kb + ty + i) * 512 + nloc + tx];
    __syncthreads();
#pragma unroll
    for (int i = 0; i < 32; i += 8)
        out[(size_t)(nb + ty + i) * 512 + kb + tx] = __float2half(t[tx][ty + i]);
}

__global__ void pack_bias(const float* __restrict__ bq, const float* __restrict__ bk,
                          const float* __restrict__ bv, float* __restrict__ bias)
{
    int i = blockIdx.x * blockDim.x + threadIdx.x;
    if (i < 1536) {
        int s = i >> 9, c = i & 511;
        const float* bs = (s == 0) ? bq : (s == 1) ? bk : bv;
        bias[i] = bs[c];
    }
}

// ---------------------------------------------------------------------------
// fp16 tensor-core GEMM (mma.sync m16n8k16, fp32 accumulate).  (unchanged R6)
// ---------------------------------------------------------------------------
#define STAGES 3
#define ROW_BYTES 80                  // 40 halves/row (32 data + 8 pad)
#define A_BYTES (128 * ROW_BYTES)     // 10240
#define STAGE_BYTES (2 * A_BYTES)     // 20480
#define GEMM_SMEM_BYTES (STAGES * STAGE_BYTES)  // 61440

#define GEMM_ISSUE(s_) do {                                                   \
    int ko_ = (s_) << 5;                                                      \
    unsigned sb_ = sbase + (unsigned)(((s_) % STAGES) * STAGE_BYTES);         \
    _Pragma("unroll")                                                         \
    for (int i_ = 0; i_ < 2; i_++) cp16(sb_ + a_sm[i_], a_gm[i_] + ko_);      \
    _Pragma("unroll")                                                         \
    for (int i_ = 0; i_ < 2; i_++)                                            \
        cp16(sb_ + A_BYTES + b_sm[i_], b_gm[i_] + ko_);                       \
} while (0)

template<bool GATHER_A, bool RELU, bool OUT_HALF>
__global__ __launch_bounds__(256, 2)
void hgemm(const __half* __restrict__ A, const __half* __restrict__ BT,
           const float* __restrict__ bias, void* __restrict__ Cv,
           int M, int N, int K)
{
    extern __shared__ unsigned char dsm[];
    const unsigned sbase = (unsigned)__cvta_generic_to_shared(dsm);

    const int tid  = threadIdx.x;
    const int row0 = blockIdx.y << 7;
    const int col0 = blockIdx.x << 7;
    const int lane = tid & 31;
    const int w    = tid >> 5;
    const int wm   = w & 1;
    const int wn   = w >> 1;
    const int tig  = lane & 3;
    const int grp  = lane >> 2;

    unsigned a_sm[2], b_sm[2];
    const __half* a_gm[2];
    const __half* b_gm[2];
#pragma unroll
    for (int i = 0; i < 2; i++) {
        int ci = tid + (i << 8);
        int r  = ci >> 2;
        int kc = (ci & 3) << 3;
        a_sm[i] = (unsigned)(r * ROW_BYTES + (kc << 1));
        b_sm[i] = a_sm[i];
        int grow = row0 + r;
        if (GATHER_A) {
            int bg = grow >> 9, l = grow & 511;
            int b  = bg & 15,  g = bg >> 4;
            a_gm[i] = A + (((size_t)b * 512 + l) * 1024 + (size_t)g * 512) + kc;
        } else {
            a_gm[i] = A + (size_t)grow * (size_t)K + kc;
        }
        b_gm[i] = BT + (size_t)(col0 + r) * (size_t)K + kc;
    }

    float acc[4][4][4];
#pragma unroll
    for (int mi = 0; mi < 4; mi++)
#pragma unroll
        for (int ni = 0; ni < 4; ni++)
#pragma unroll
            for (int j = 0; j < 4; j++) acc[mi][ni][j] = 0.f;

    GEMM_ISSUE(0); cp_commit();
    GEMM_ISSUE(1); cp_commit();

    const int nIter = K >> 5;
    for (int it = 0; it < nIter; ++it) {
        cp_wait<1>();
        __syncthreads();

        const unsigned* Aw = (const unsigned*)(dsm + (it % STAGES) * STAGE_BYTES);
        const unsigned* Bw = (const unsigned*)(dsm + (it % STAGES) * STAGE_BYTES + A_BYTES);
#pragma unroll
        for (int ks = 0; ks < 2; ks++) {
            unsigned af[4][4], bf[4][2];
#pragma unroll
            for (int mi = 0; mi < 4; mi++) {
                const unsigned* p = Aw + ((wm << 6) + (mi << 4) + grp) * 20
                                       + (ks << 3) + tig;
                af[mi][0] = p[0];
                af[mi][1] = p[160];
                af[mi][2] = p[4];
                af[mi][3] = p[164];
            }
#pragma unroll
            for (int ni = 0; ni < 4; ni++) {
                const unsigned* p = Bw + ((wn << 5) + (ni << 3) + grp) * 20
                                       + (ks << 3) + tig;
                bf[ni][0] = p[0];
                bf[ni][1] = p[4];
            }
#pragma unroll
            for (int mi = 0; mi < 4; mi++)
#pragma unroll
                for (int ni = 0; ni < 4; ni++)
                    mma_f16(acc[mi][ni], af[mi], bf[ni]);
        }

        int s = it + 2;
        if (s < nIter) GEMM_ISSUE(s);
        cp_commit();
    }

#pragma unroll
    for (int mi = 0; mi < 4; mi++) {
        int r = row0 + (wm << 6) + (mi << 4) + grp;
#pragma unroll
        for (int ni = 0; ni < 4; ni++) {
            int c = col0 + (wn << 5) + (ni << 3) + (tig << 1);
            float2 bv = *(const float2*)&bias[c];
            float v00 = acc[mi][ni][0] + bv.x;
            float v01 = acc[mi][ni][1] + bv.y;
            float v10 = acc[mi][ni][2] + bv.x;
            float v11 = acc[mi][ni][3] + bv.y;
            if (RELU) {
                v00 = fmaxf(v00, 0.f); v01 = fmaxf(v01, 0.f);
                v10 = fmaxf(v10, 0.f); v11 = fmaxf(v11, 0.f);
            }
            if (OUT_HALF) {
                __half* Ch = (__half*)Cv;
                *(__half2*)&Ch[(size_t)r * N + c]       = __floats2half2_rn(v00, v01);
                *(__half2*)&Ch[(size_t)(r + 8) * N + c] = __floats2half2_rn(v10, v11);
            } else {
                float* Cf = (float*)Cv;
                float2 o0; o0.x = v00; o0.y = v01;
                float2 o1; o1.x = v10; o1.y = v11;
                *(float2*)&Cf[(size_t)r * N + c]       = o0;
                *(float2*)&Cf[(size_t)(r + 8) * N + c] = o1;
            }
        }
    }
}

// ---------------------------------------------------------------------------
// Tensor-core attention.  Grid = 512 blocks = (bg, head).  256 threads.
// Q/K/V (256x64 fp16) in smem pitch 72 halves (ldmatrix conflict-free).
// Two q-passes of 128 rows; each warp owns 16 q rows per pass:
//   S = Q K^T via m16n8k16 (32 n-tiles, 4 k-steps), softmax in registers
//   (quad shfl; 1/sum folded into epilogue), P reused directly as A-fragments
//   for O = P V (V B-frags via ldmatrix.x4.trans).  Output -> att half layout.
// ---------------------------------------------------------------------------
#define ATTN_THREADS 256
#define QKV_STRIDE 1536
#define QP 72
#define ATTN_SMEM_BYTES (3 * 256 * QP * 2)   // 110592

__global__ __launch_bounds__(ATTN_THREADS, 1)
void attn_mma(const __half* __restrict__ qkv, const void* __restrict__ maskp,
              __half* __restrict__ atted)
{
    extern __shared__ __half hs[];
    __half* Qs = hs;
    __half* Ks = Qs + 256 * QP;
    __half* Vs = Ks + 256 * QP;
    __shared__ float mvals[256];

    const int bg   = blockIdx.x >> 4;
    const int h    = blockIdx.x & 15;
    const int tid  = threadIdx.x;
    const int lane = tid & 31;
    const int w    = tid >> 5;
    const int lpar  = h >> 3;
    const int cbase = (h & 7) << 6;
    const int b = bg & 15;
    const int g = bg >> 4;

    // mask dtype detection (any word > 1 => byte-packed bools)
    unsigned word = ((const unsigned*)maskp)[tid];
    int is32 = __syncthreads_and(word <= 1u);

    const __half* base = qkv + (size_t)bg * 512 * QKV_STRIDE;

    // Load Q/K/V tiles: 2048 uint4 chunks each (8 halves per chunk)
    for (int idx = tid; idx < 2048; idx += ATTN_THREADS) {
        int t  = idx >> 3;
        int d8 = (idx & 7) << 3;
        size_t off = (size_t)(2 * t + lpar) * QKV_STRIDE + cbase + d8;
        *(uint4*)&Qs[t * QP + d8] = *(const uint4*)(base + off);
        *(uint4*)&Ks[t * QP + d8] = *(const uint4*)(base + 512 + off);
        *(uint4*)&Vs[t * QP + d8] = *(const uint4*)(base + 1024 + off);
    }
    {
        int mv = is32 ? ((const int*)maskp)[b * 256 + tid]
                      : (int)((const unsigned char*)maskp)[b * 256 + tid];
        mvals[tid] = mv ? -1e9f : 0.0f;
    }
    __syncthreads();

    const unsigned qs0 = (unsigned)__cvta_generic_to_shared(Qs);
    const unsigned ks0 = (unsigned)__cvta_generic_to_shared(Ks);
    const unsigned vs0 = (unsigned)__cvta_generic_to_shared(Vs);

    const int lq = lane >> 2;        // fragment row within m16
    const int lc = (lane & 3) << 1;  // fragment col pair base

#pragma unroll 1
    for (int pass = 0; pass < 2; pass++) {
        const int qrow0 = pass * 128 + w * 16;

        // --- A fragments of Q (4 k-steps) ---
        unsigned aq[4][4];
#pragma unroll
        for (int ks = 0; ks < 4; ks++) {
            unsigned addr = qs0 + (unsigned)(((qrow0 + (lane & 15)) * QP
                              + (ks << 4) + ((lane >> 4) << 3)) * 2);
            ldsm_x4(aq[ks], addr);
        }

        // --- S = Q K^T : 32 n-tiles x 4 f32 ---
        float acc[32][4];
#pragma unroll
        for (int nt = 0; nt < 32; nt++) {
            acc[nt][0] = 0.f; acc[nt][1] = 0.f; acc[nt][2] = 0.f; acc[nt][3] = 0.f;
            unsigned bk[2][4];
#pragma unroll
            for (int j = 0; j < 2; j++) {
                unsigned addr = ks0 + (unsigned)((((nt << 3) + (lane & 7)) * QP
                                  + (j << 5) + ((lane >> 3) << 3)) * 2);
                ldsm_x4(bk[j], addr);
            }
            mma_f16(acc[nt], aq[0], &bk[0][0]);
            mma_f16(acc[nt], aq[1], &bk[0][2]);
            mma_f16(acc[nt], aq[2], &bk[1][0]);
            mma_f16(acc[nt], aq[3], &bk[1][2]);
        }

        // --- scale + mask + row max (rows lq and lq+8) ---
        const float scale = 0.125f;
        float m0 = -3.0e38f, m1 = -3.0e38f;
#pragma unroll
        for (int nt = 0; nt < 32; nt++) {
            float mv0 = mvals[(nt << 3) + lc];
            float mv1 = mvals[(nt << 3) + lc + 1];
            acc[nt][0] = acc[nt][0] * scale + mv0;
            acc[nt][1] = acc[nt][1] * scale + mv1;
            acc[nt][2] = acc[nt][2] * scale + mv0;
            acc[nt][3] = acc[nt][3] * scale + mv1;
            m0 = fmaxf(m0, fmaxf(acc[nt][0], acc[nt][1]));
            m1 = fmaxf(m1, fmaxf(acc[nt][2], acc[nt][3]));
        }
        m0 = fmaxf(m0, __shfl_xor_sync(0xffffffffu, m0, 1));
        m0 = fmaxf(m0, __shfl_xor_sync(0xffffffffu, m0, 2));
        m1 = fmaxf(m1, __shfl_xor_sync(0xffffffffu, m1, 1));
        m1 = fmaxf(m1, __shfl_xor_sync(0xffffffffu, m1, 2));

        // --- exp + row sums ---
        float s0 = 0.f, s1 = 0.f;
#pragma unroll
        for (int nt = 0; nt < 32; nt++) {
            acc[nt][0] = __expf(acc[nt][0] - m0);
            acc[nt][1] = __expf(acc[nt][1] - m0);
            acc[nt][2] = __expf(acc[nt][2] - m1);
            acc[nt][3] = __expf(acc[nt][3] - m1);
            s0 += acc[nt][0] + acc[nt][1];
            s1 += acc[nt][2] + acc[nt][3];
        }
        s0 += __shfl_xor_sync(0xffffffffu, s0, 1);
        s0 += __shfl_xor_sync(0xffffffffu, s0, 2);
        s1 += __shfl_xor_sync(0xffffffffu, s1, 1);
        s1 += __shfl_xor_sync(0xffffffffu, s1, 2);
        const float inv0 = 1.f / s0;
        const float inv1 = 1.f / s1;

        // --- O = P V : 8 n-tiles (d) x 4 f32, P from registers ---
        float o[8][4];
#pragma unroll
        for (int dn = 0; dn < 8; dn++) {
            o[dn][0] = 0.f; o[dn][1] = 0.f; o[dn][2] = 0.f; o[dn][3] = 0.f;
        }
#pragma unroll
        for (int kt = 0; kt < 16; kt++) {
            unsigned pa[4];
            __half2 p0 = __floats2half2_rn(acc[2*kt][0],   acc[2*kt][1]);
            __half2 p1 = __floats2half2_rn(acc[2*kt][2],   acc[2*kt][3]);
            __half2 p2 = __floats2half2_rn(acc[2*kt+1][0], acc[2*kt+1][1]);
            __half2 p3 = __floats2half2_rn(acc[2*kt+1][2], acc[2*kt+1][3]);
            pa[0] = *(unsigned*)&p0; pa[1] = *(unsigned*)&p1;
            pa[2] = *(unsigned*)&p2; pa[3] = *(unsigned*)&p3;
#pragma unroll
            for (int p = 0; p < 4; p++) {
                unsigned bv[4];
                unsigned addr = vs0 + (unsigned)((((kt << 4) + ((lane >> 3) & 1) * 8
                                  + (lane & 7)) * QP
                                  + (p << 4) + ((lane >> 4) << 3)) * 2);
                ldsm_x4_t(bv, addr);
                mma_f16(o[2*p],     pa, &bv[0]);
                mma_f16(o[2*p + 1], pa, &bv[2]);
            }
        }

        // --- store (fold 1/sum), att (B,L,H) half layout ---
        const int t0 = qrow0 + lq;
#pragma unroll
        for (int dn = 0; dn < 8; dn++) {
            int d = (dn << 3) + lc;
            __half2 h0 = __floats2half2_rn(o[dn][0] * inv0, o[dn][1] * inv0);
            __half2 h1 = __floats2half2_rn(o[dn][2] * inv1, o[dn][3] * inv1);
            size_t ob0 = ((size_t)b * 512 + (2 * t0 + lpar)) * 1024
                       + (size_t)g * 512 + cbase + d;
            size_t ob1 = ((size_t)b * 512 + (2 * (t0 + 8) + lpar)) * 1024
                       + (size_t)g * 512 + cbase + d;
            *(__half2*)&atted[ob0] = h0;
            *(__half2*)&atted[ob1] = h1;
        }
    }
}

// ---------------------------------------------------------------------------
// Residual-add + LayerNorm over rows of 1024. One block (256 thr) per row.
// ---------------------------------------------------------------------------
__global__ __launch_bounds__(256)
void add_ln_kernel(const float* __restrict__ res, const float* __restrict__ dlt,
                   const float* __restrict__ gamma, const float* __restrict__ beta,
                   float* __restrict__ out, __half* __restrict__ outh)
{
    __shared__ float red[8];
    __shared__ float s_mean, s_inv;
    const int row = blockIdx.x;
    const int tid = threadIdx.x;
    const size_t base = (size_t)row * 1024;

    float x[4];
    float s = 0.f;
#pragma unroll
    for (int i = 0; i < 4; i++) {
        int c = tid + (i << 8);
        x[i] = res[base + c] + dlt[base + c];
        s += x[i];
    }
#pragma unroll
    for (int o = 16; o; o >>= 1) s += __shfl_xor_sync(0xffffffffu, s, o);
    if ((tid & 31) == 0) red[tid >> 5] = s;
    __syncthreads();
    if (tid < 32) {
        float t = (tid < 8) ? red[tid] : 0.f;
#pragma unroll
        for (int o = 4; o; o >>= 1) t += __shfl_xor_sync(0xffffffffu, t, o);
        if (tid == 0) s_mean = t * (1.f / 1024.f);
    }
    __syncthreads();
    const float mean = s_mean;

    float vs = 0.f;
#pragma unroll
    for (int i = 0; i < 4; i++) { float d = x[i] - mean; vs += d * d; }
#pragma unroll
    for (int o = 16; o; o >>= 1) vs += __shfl_xor_sync(0xffffffffu, vs, o);
    if ((tid & 31) == 0) red[tid >> 5] = vs;
    __syncthreads();
    if (tid < 32) {
        float t = (tid < 8) ? red[tid] : 0.f;
#pragma unroll
        for (int o = 4; o; o >>= 1) t += __shfl_xor_sync(0xffffffffu, t, o);
        if (tid == 0) s_inv = rsqrtf(t * (1.f / 1024.f) + 1e-6f);
    }
    __syncthreads();
    const float inv = s_inv;

#pragma unroll
    for (int i = 0; i < 4; i++) {
        int c = tid + (i << 8);
        float v = (x[i] - mean) * inv * gamma[c] + beta[c];
        out[base + c] = v;
        if (outh) outh[base + c] = __float2half(v);
    }
}

// ---------------------------------------------------------------------------
// Launch
// ---------------------------------------------------------------------------
extern "C" void kernel_launch(void* const* d_in, const int* in_sizes, int n_in,
                              void* d_out, int out_size)
{
    const float* y   = (const float*)d_in[0];
    const void*  msk = d_in[1];
    const float* Wv  = (const float*)d_in[2];
    const float* bv  = (const float*)d_in[3];
    const float* Wk  = (const float*)d_in[4];
    const float* bk  = (const float*)d_in[5];
    const float* Wq  = (const float*)d_in[6];
    const float* bq  = (const float*)d_in[7];
    const float* Wm  = (const float*)d_in[8];
    const float* bm  = (const float*)d_in[9];
    const float* W1  = (const float*)d_in[10];
    const float* b1  = (const float*)d_in[11];
    const float* W2  = (const float*)d_in[12];
    const float* b2  = (const float*)d_in[13];
    const float* g1  = (const float*)d_in[14];
    const float* be1 = (const float*)d_in[15];
    const float* g2  = (const float*)d_in[16];
    const float* be2 = (const float*)d_in[17];
    float* out = (float*)d_out;

    __half *yh, *wqkvT, *wmT, *w1T, *w2T, *qkv, *att, *y1h, *h1;
    float *bqkv, *mh, *y1, *ff;
    cudaGetSymbolAddress((void**)&yh,    g_yh);
    cudaGetSymbolAddress((void**)&wqkvT, g_wqkvT);
    cudaGetSymbolAddress((void**)&bqkv,  g_bqkv);
    cudaGetSymbolAddress((void**)&wmT,   g_wmT);
    cudaGetSymbolAddress((void**)&w1T,   g_w1T);
    cudaGetSymbolAddress((void**)&w2T,   g_w2T);
    cudaGetSymbolAddress((void**)&qkv,   g_qkv);
    cudaGetSymbolAddress((void**)&att,   g_att);
    cudaGetSymbolAddress((void**)&mh,    g_mh);
    cudaGetSymbolAddress((void**)&y1,    g_y1);
    cudaGetSymbolAddress((void**)&y1h,   g_y1h);
    cudaGetSymbolAddress((void**)&h1,    g_h1);
    cudaGetSymbolAddress((void**)&ff,    g_ff);

    cudaFuncSetAttribute(attn_mma,
                         cudaFuncAttributeMaxDynamicSharedMemorySize, ATTN_SMEM_BYTES);
    cudaFuncSetAttribute(hgemm<true,  false, true >,
                         cudaFuncAttributeMaxDynamicSharedMemorySize, GEMM_SMEM_BYTES);
    cudaFuncSetAttribute(hgemm<false, false, false>,
                         cudaFuncAttributeMaxDynamicSharedMemorySize, GEMM_SMEM_BYTES);
    cudaFuncSetAttribute(hgemm<false, true,  true >,
                         cudaFuncAttributeMaxDynamicSharedMemorySize, GEMM_SMEM_BYTES);

    dim3 blk(256);
    dim3 tblk(32, 8);

    // Pre-passes: y -> half; weights -> transposed (N,K) half; pack qkv bias
    cvt_half<<<2048, 512>>>(y, yh, 16*512*1024);
    transp_qkv<<<dim3(48, 16),  tblk>>>(Wq, Wk, Wv, wqkvT);
    pack_bias<<<3, 512>>>(bq, bk, bv, bqkv);
    transp<<<dim3(32, 32),  tblk>>>(Wm, wmT, 1024, 1024);
    transp<<<dim3(128, 32), tblk>>>(W1, w1T, 1024, 4096);
    transp<<<dim3(16, 64),  tblk>>>(W2, w2T, 2048, 512);

    // Fused QKV: (16384,1536) = gather(yh) @ Wqkv + bqkv  -> half
    hgemm<true,  false, true ><<<dim3(12, 128), blk, GEMM_SMEM_BYTES>>>(yh, wqkvT, bqkv, qkv, 16384, 1536, 512);

    // Tensor-core attention -> att (half, B,L,H layout)
    attn_mma<<<512, ATTN_THREADS, ATTN_SMEM_BYTES>>>(qkv, msk, att);

    // Merge: (8192,1024) @ Wm + bm -> fp32
    hgemm<false, false, false><<<dim3(8, 64), blk, GEMM_SMEM_BYTES>>>(att, wmT, bm, mh, 8192, 1024, 1024);

    // y1 = LN(y + merge): fp32 (residual) + half (FFN1 input)
    add_ln_kernel<<<8192, blk>>>(y, mh, g1, be1, y1, y1h);

    // FFN1: (8192,1024) @ W1 + b1, relu -> half
    hgemm<false, true,  true ><<<dim3(32, 64), blk, GEMM_SMEM_BYTES>>>(y1h, w1T, b1, h1, 8192, 4096, 1024);

    // FFN2 (grouped == contiguous reinterpret): (16384,2048) @ W2 + b2 -> fp32
    hgemm<false, false, false><<<dim3(4, 128), blk, GEMM_SMEM_BYTES>>>(h1, w2T, b2, ff, 16384, 512, 2048);

    // out = LN(y1 + ff), full fp32
    add_ln_kernel<<<8192, blk>>>(y1, ff, g2, be2, out, (__half*)0);
}

// round 8
// speedup vs baseline: 2.0962x; 1.0513x over previous
#include <cuda_runtime.h>
#include <cuda_fp16.h>
#include <math.h>
#include <stdint.h>

// ---------------------------------------------------------------------------
// Problem constants: B=16, L=512, H=1024, G=2, NH=16, DH=64, FF=4096,
//                    DM=512, LG=256
// ---------------------------------------------------------------------------

// Scratch (device globals; allocation inside kernel_launch is forbidden)
__device__ __half g_yh   [16u*512u*1024u];   // half copy of y (GEMM A input)
__device__ __half g_wqkvT[1536u*512u];       // (N,K) transposed packed Wq|Wk|Wv
__device__ float  g_bqkv [1536u];
__device__ __half g_wmT  [1024u*1024u];      // (N,K)
__device__ __half g_w1T  [4096u*1024u];
__device__ __half g_w2T  [512u*2048u];
__device__ __half g_qkv  [16384u*1536u];     // fused QKV output (row stride 1536)
__device__ __half g_att  [16u*512u*1024u];   // attention output (GEMM A input)
__device__ float  g_mh   [16u*512u*1024u];
__device__ float  g_y1   [16u*512u*1024u];   // LN1 out fp32 (residual)
__device__ __half g_y1h  [16u*512u*1024u];   // LN1 out half (FFN1 A input)
__device__ __half g_h1   [8192u*4096u];      // FFN hidden (relu, half)
__device__ float  g_ff   [16u*512u*1024u];

// ---------------------------------------------------------------------------
// Helpers
// ---------------------------------------------------------------------------
__device__ __forceinline__ void mma_f16(float* d, const unsigned* a, const unsigned* b) {
    asm volatile(
        "mma.sync.aligned.m16n8k16.row.col.f32.f16.f16.f32 "
        "{%0,%1,%2,%3}, {%4,%5,%6,%7}, {%8,%9}, {%0,%1,%2,%3};\n"
        : "+f"(d[0]), "+f"(d[1]), "+f"(d[2]), "+f"(d[3])
        : "r"(a[0]), "r"(a[1]), "r"(a[2]), "r"(a[3]), "r"(b[0]), "r"(b[1]));
}

__device__ __forceinline__ void ldsm_x4(unsigned* r, unsigned a) {
    asm volatile("ldmatrix.sync.aligned.m8n8.x4.shared.b16 {%0,%1,%2,%3}, [%4];"
        : "=r"(r[0]), "=r"(r[1]), "=r"(r[2]), "=r"(r[3]) : "r"(a));
}
__device__ __forceinline__ void ldsm_x4_t(unsigned* r, unsigned a) {
    asm volatile("ldmatrix.sync.aligned.m8n8.x4.trans.shared.b16 {%0,%1,%2,%3}, [%4];"
        : "=r"(r[0]), "=r"(r[1]), "=r"(r[2]), "=r"(r[3]) : "r"(a));
}

__device__ __forceinline__ void cp16(unsigned dst, const void* src) {
    asm volatile("cp.async.cg.shared.global [%0], [%1], 16;\n" :: "r"(dst), "l"(src));
}
__device__ __forceinline__ void cp_commit() {
    asm volatile("cp.async.commit_group;\n" ::);
}
template<int N>
__device__ __forceinline__ void cp_wait() {
    asm volatile("cp.async.wait_group %0;\n" :: "n"(N));
}

// ---------------------------------------------------------------------------
// Pre-passes
// ---------------------------------------------------------------------------
__global__ void cvt_half(const float* __restrict__ in, __half* __restrict__ out, int n)
{
    int i = blockIdx.x * blockDim.x + threadIdx.x;
    int stride = gridDim.x * blockDim.x;
    for (; i < n; i += stride) out[i] = __float2half(in[i]);
}

// Tiled transpose + half convert: in[K,N] fp32 -> out[N,K] half
__global__ void transp(const float* __restrict__ in, __half* __restrict__ out,
                       int K, int N)
{
    __shared__ float t[32][33];
    int nb = blockIdx.x << 5, kb = blockIdx.y << 5;
    int tx = threadIdx.x, ty = threadIdx.y;
#pragma unroll
    for (int i = 0; i < 32; i += 8)
        t[ty + i][tx] = in[(size_t)(kb + ty + i) * N + nb + tx];
    __syncthreads();
#pragma unroll
    for (int i = 0; i < 32; i += 8)
        out[(size_t)(nb + ty + i) * K + kb + tx] = __float2half(t[tx][ty + i]);
}

// Transpose+convert+pack Wq|Wk|Wv (each 512x512) -> out (1536, 512) half
__global__ void transp_qkv(const float* __restrict__ Wq, const float* __restrict__ Wk,
                           const float* __restrict__ Wv, __half* __restrict__ out)
{
    __shared__ float t[32][33];
    int nb = blockIdx.x << 5, kb = blockIdx.y << 5;
    const float* src = (nb < 512) ? Wq : (nb < 1024) ? Wk : Wv;
    int nloc = nb & 511;
    int tx = threadIdx.x, ty = threadIdx.y;
#pragma unroll
    for (int i = 0; i < 32; i += 8)
        t[ty + i][tx] = src[(size_t)(kb + ty + i) * 512 + nloc + tx];
    __syncthreads();
#pragma unroll
    for (int i = 0; i < 32; i += 8)
        out[(size_t)(nb + ty + i) * 512 + kb + tx] = __float2half(t[tx][ty + i]);
}

__global__ void pack_bias(const float* __restrict__ bq, const float* __restrict__ bk,
                          const float* __restrict__ bv, float* __restrict__ bias)
{
    int i = blockIdx.x * blockDim.x + threadIdx.x;
    if (i < 1536) {
        int s = i >> 9, c = i & 511;
        const float* bs = (s == 0) ? bq : (s == 1) ? bk : bv;
        bias[i] = bs[c];
    }
}

// ---------------------------------------------------------------------------
// fp16 tensor-core GEMM (mma.sync m16n8k16, fp32 accumulate).
// Block tile 128x128, K-step 32 halves, 256 threads, 8 warps 2(M)x4(N),
// warp tile 64x32.  Fragments via ldmatrix.x4 (12 LDSM : 32 HMMA per k-tile;
// pitch-40-half rows are ldmatrix conflict-free).  3-stage cp.async, 60KB
// smem -> 2 CTAs/SM.  BT is the pre-transposed (N,K) weight.
// Requires M%128==0, N%128==0, K%32==0.
// ---------------------------------------------------------------------------
#define STAGES 3
#define ROW_BYTES 80                  // 40 halves/row (32 data + 8 pad)
#define A_BYTES (128 * ROW_BYTES)     // 10240
#define STAGE_BYTES (2 * A_BYTES)     // 20480
#define GEMM_SMEM_BYTES (STAGES * STAGE_BYTES)  // 61440

#define GEMM_ISSUE(s_) do {                                                   \
    int ko_ = (s_) << 5;                                                      \
    unsigned sb_ = sbase + (unsigned)(((s_) % STAGES) * STAGE_BYTES);         \
    _Pragma("unroll")                                                         \
    for (int i_ = 0; i_ < 2; i_++) cp16(sb_ + a_sm[i_], a_gm[i_] + ko_);      \
    _Pragma("unroll")                                                         \
    for (int i_ = 0; i_ < 2; i_++)                                            \
        cp16(sb_ + A_BYTES + b_sm[i_], b_gm[i_] + ko_);                       \
} while (0)

template<bool GATHER_A, bool RELU, bool OUT_HALF>
__global__ __launch_bounds__(256, 2)
void hgemm(const __half* __restrict__ A, const __half* __restrict__ BT,
           const float* __restrict__ bias, void* __restrict__ Cv,
           int M, int N, int K)
{
    extern __shared__ unsigned char dsm[];
    const unsigned sbase = (unsigned)__cvta_generic_to_shared(dsm);

    const int tid  = threadIdx.x;
    const int row0 = blockIdx.y << 7;
    const int col0 = blockIdx.x << 7;
    const int lane = tid & 31;
    const int w    = tid >> 5;
    const int wm   = w & 1;
    const int wn   = w >> 1;
    const int tig  = lane & 3;
    const int grp  = lane >> 2;

    unsigned a_sm[2], b_sm[2];
    const __half* a_gm[2];
    const __half* b_gm[2];
#pragma unroll
    for (int i = 0; i < 2; i++) {
        int ci = tid + (i << 8);
        int r  = ci >> 2;
        int kc = (ci & 3) << 3;
        a_sm[i] = (unsigned)(r * ROW_BYTES + (kc << 1));
        b_sm[i] = a_sm[i];
        int grow = row0 + r;
        if (GATHER_A) {
            int bg = grow >> 9, l = grow & 511;
            int b  = bg & 15,  g = bg >> 4;
            a_gm[i] = A + (((size_t)b * 512 + l) * 1024 + (size_t)g * 512) + kc;
        } else {
            a_gm[i] = A + (size_t)grow * (size_t)K + kc;
        }
        b_gm[i] = BT + (size_t)(col0 + r) * (size_t)K + kc;
    }

    // ldmatrix source addresses (fixed per thread, advance by stage)
    // A x4: rows (wm*64 + mi*16 + lane%16), k-halves ks*16 + (lane/16)*8
    // B x4: rows (wn*32 + ni*8 + lane%8),   k-halves (lane/8)*8  (n8 x k32)
    const unsigned a_ld = (unsigned)(((wm << 6) + (lane & 15)) * ROW_BYTES
                                     + (((lane >> 4) << 3) << 1));
    const unsigned b_ld = (unsigned)((((wn << 5) + (lane & 7)) * ROW_BYTES)
                                     + ((((lane >> 3) & 3) << 3) << 1));

    float acc[4][4][4];
#pragma unroll
    for (int mi = 0; mi < 4; mi++)
#pragma unroll
        for (int ni = 0; ni < 4; ni++)
#pragma unroll
            for (int j = 0; j < 4; j++) acc[mi][ni][j] = 0.f;

    GEMM_ISSUE(0); cp_commit();
    GEMM_ISSUE(1); cp_commit();

    const int nIter = K >> 5;
    for (int it = 0; it < nIter; ++it) {
        cp_wait<1>();
        __syncthreads();

        const unsigned stg = sbase + (unsigned)((it % STAGES) * STAGE_BYTES);

        // B fragments: 4 ldsm_x4, each n8 x k32 (regs: k0-7,k8-15,k16-23,k24-31)
        unsigned bf[4][4];
#pragma unroll
        for (int ni = 0; ni < 4; ni++)
            ldsm_x4(bf[ni], stg + A_BYTES + b_ld + (unsigned)(ni * 8 * ROW_BYTES));

#pragma unroll
        for (int ks = 0; ks < 2; ks++) {
            unsigned af[4][4];
#pragma unroll
            for (int mi = 0; mi < 4; mi++)
                ldsm_x4(af[mi], stg + a_ld
                        + (unsigned)(mi * 16 * ROW_BYTES + (ks << 5)));
#pragma unroll
            for (int mi = 0; mi < 4; mi++)
#pragma unroll
                for (int ni = 0; ni < 4; ni++)
                    mma_f16(acc[mi][ni], af[mi], &bf[ni][ks << 1]);
        }

        int s = it + 2;
        if (s < nIter) GEMM_ISSUE(s);
        cp_commit();
    }

#pragma unroll
    for (int mi = 0; mi < 4; mi++) {
        int r = row0 + (wm << 6) + (mi << 4) + grp;
#pragma unroll
        for (int ni = 0; ni < 4; ni++) {
            int c = col0 + (wn << 5) + (ni << 3) + (tig << 1);
            float2 bv = *(const float2*)&bias[c];
            float v00 = acc[mi][ni][0] + bv.x;
            float v01 = acc[mi][ni][1] + bv.y;
            float v10 = acc[mi][ni][2] + bv.x;
            float v11 = acc[mi][ni][3] + bv.y;
            if (RELU) {
                v00 = fmaxf(v00, 0.f); v01 = fmaxf(v01, 0.f);
                v10 = fmaxf(v10, 0.f); v11 = fmaxf(v11, 0.f);
            }
            if (OUT_HALF) {
                __half* Ch = (__half*)Cv;
                *(__half2*)&Ch[(size_t)r * N + c]       = __floats2half2_rn(v00, v01);
                *(__half2*)&Ch[(size_t)(r + 8) * N + c] = __floats2half2_rn(v10, v11);
            } else {
                float* Cf = (float*)Cv;
                float2 o0; o0.x = v00; o0.y = v01;
                float2 o1; o1.x = v10; o1.y = v11;
                *(float2*)&Cf[(size_t)r * N + c]       = o0;
                *(float2*)&Cf[(size_t)(r + 8) * N + c] = o1;
            }
        }
    }
}

// ---------------------------------------------------------------------------
// Tensor-core attention (unchanged from R7).
// ---------------------------------------------------------------------------
#define ATTN_THREADS 256
#define QKV_STRIDE 1536
#define QP 72
#define ATTN_SMEM_BYTES (3 * 256 * QP * 2)   // 110592

__global__ __launch_bounds__(ATTN_THREADS, 1)
void attn_mma(const __half* __restrict__ qkv, const void* __restrict__ maskp,
              __half* __restrict__ atted)
{
    extern __shared__ __half hs[];
    __half* Qs = hs;
    __half* Ks = Qs + 256 * QP;
    __half* Vs = Ks + 256 * QP;
    __shared__ float mvals[256];

    const int bg   = blockIdx.x >> 4;
    const int h    = blockIdx.x & 15;
    const int tid  = threadIdx.x;
    const int lane = tid & 31;
    const int w    = tid >> 5;
    const int lpar  = h >> 3;
    const int cbase = (h & 7) << 6;
    const int b = bg & 15;
    const int g = bg >> 4;

    unsigned word = ((const unsigned*)maskp)[tid];
    int is32 = __syncthreads_and(word <= 1u);

    const __half* base = qkv + (size_t)bg * 512 * QKV_STRIDE;

    for (int idx = tid; idx < 2048; idx += ATTN_THREADS) {
        int t  = idx >> 3;
        int d8 = (idx & 7) << 3;
        size_t off = (size_t)(2 * t + lpar) * QKV_STRIDE + cbase + d8;
        *(uint4*)&Qs[t * QP + d8] = *(const uint4*)(base + off);
        *(uint4*)&Ks[t * QP + d8] = *(const uint4*)(base + 512 + off);
        *(uint4*)&Vs[t * QP + d8] = *(const uint4*)(base + 1024 + off);
    }
    {
        int mv = is32 ? ((const int*)maskp)[b * 256 + tid]
                      : (int)((const unsigned char*)maskp)[b * 256 + tid];
        mvals[tid] = mv ? -1e9f : 0.0f;
    }
    __syncthreads();

    const unsigned qs0 = (unsigned)__cvta_generic_to_shared(Qs);
    const unsigned ks0 = (unsigned)__cvta_generic_to_shared(Ks);
    const unsigned vs0 = (unsigned)__cvta_generic_to_shared(Vs);

    const int lq = lane >> 2;
    const int lc = (lane & 3) << 1;

#pragma unroll 1
    for (int pass = 0; pass < 2; pass++) {
        const int qrow0 = pass * 128 + w * 16;

        unsigned aq[4][4];
#pragma unroll
        for (int ks = 0; ks < 4; ks++) {
            unsigned addr = qs0 + (unsigned)(((qrow0 + (lane & 15)) * QP
                              + (ks << 4) + ((lane >> 4) << 3)) * 2);
            ldsm_x4(aq[ks], addr);
        }

        float acc[32][4];
#pragma unroll
        for (int nt = 0; nt < 32; nt++) {
            acc[nt][0] = 0.f; acc[nt][1] = 0.f; acc[nt][2] = 0.f; acc[nt][3] = 0.f;
            unsigned bk[2][4];
#pragma unroll
            for (int j = 0; j < 2; j++) {
                unsigned addr = ks0 + (unsigned)((((nt << 3) + (lane & 7)) * QP
                                  + (j << 5) + ((lane >> 3) << 3)) * 2);
                ldsm_x4(bk[j], addr);
            }
            mma_f16(acc[nt], aq[0], &bk[0][0]);
            mma_f16(acc[nt], aq[1], &bk[0][2]);
            mma_f16(acc[nt], aq[2], &bk[1][0]);
            mma_f16(acc[nt], aq[3], &bk[1][2]);
        }

        const float scale = 0.125f;
        float m0 = -3.0e38f, m1 = -3.0e38f;
#pragma unroll
        for (int nt = 0; nt < 32; nt++) {
            float mv0 = mvals[(nt << 3) + lc];
            float mv1 = mvals[(nt << 3) + lc + 1];
            acc[nt][0] = acc[nt][0] * scale + mv0;
            acc[nt][1] = acc[nt][1] * scale + mv1;
            acc[nt][2] = acc[nt][2] * scale + mv0;
            acc[nt][3] = acc[nt][3] * scale + mv1;
            m0 = fmaxf(m0, fmaxf(acc[nt][0], acc[nt][1]));
            m1 = fmaxf(m1, fmaxf(acc[nt][2], acc[nt][3]));
        }
        m0 = fmaxf(m0, __shfl_xor_sync(0xffffffffu, m0, 1));
        m0 = fmaxf(m0, __shfl_xor_sync(0xffffffffu, m0, 2));
        m1 = fmaxf(m1, __shfl_xor_sync(0xffffffffu, m1, 1));
        m1 = fmaxf(m1, __shfl_xor_sync(0xffffffffu, m1, 2));

        float s0 = 0.f, s1 = 0.f;
#pragma unroll
        for (int nt = 0; nt < 32; nt++) {
            acc[nt][0] = __expf(acc[nt][0] - m0);
            acc[nt][1] = __expf(acc[nt][1] - m0);
            acc[nt][2] = __expf(acc[nt][2] - m1);
            acc[nt][3] = __expf(acc[nt][3] - m1);
            s0 += acc[nt][0] + acc[nt][1];
            s1 += acc[nt][2] + acc[nt][3];
        }
        s0 += __shfl_xor_sync(0xffffffffu, s0, 1);
        s0 += __shfl_xor_sync(0xffffffffu, s0, 2);
        s1 += __shfl_xor_sync(0xffffffffu, s1, 1);
        s1 += __shfl_xor_sync(0xffffffffu, s1, 2);
        const float inv0 = 1.f / s0;
        const float inv1 = 1.f / s1;

        float o[8][4];
#pragma unroll
        for (int dn = 0; dn < 8; dn++) {
            o[dn][0] = 0.f; o[dn][1] = 0.f; o[dn][2] = 0.f; o[dn][3] = 0.f;
        }
#pragma unroll
        for (int kt = 0; kt < 16; kt++) {
            unsigned pa[4];
            __half2 p0 = __floats2half2_rn(acc[2*kt][0],   acc[2*kt][1]);
            __half2 p1 = __floats2half2_rn(acc[2*kt][2],   acc[2*kt][3]);
            __half2 p2 = __floats2half2_rn(acc[2*kt+1][0], acc[2*kt+1][1]);
            __half2 p3 = __floats2half2_rn(acc[2*kt+1][2], acc[2*kt+1][3]);
            pa[0] = *(unsigned*)&p0; pa[1] = *(unsigned*)&p1;
            pa[2] = *(unsigned*)&p2; pa[3] = *(unsigned*)&p3;
#pragma unroll
            for (int p = 0; p < 4; p++) {
                unsigned bv[4];
                unsigned addr = vs0 + (unsigned)((((kt << 4) + ((lane >> 3) & 1) * 8
                                  + (lane & 7)) * QP
                                  + (p << 4) + ((lane >> 4) << 3)) * 2);
                ldsm_x4_t(bv, addr);
                mma_f16(o[2*p],     pa, &bv[0]);
                mma_f16(o[2*p + 1], pa, &bv[2]);
            }
        }

        const int t0 = qrow0 + lq;
#pragma unroll
        for (int dn = 0; dn < 8; dn++) {
            int d = (dn << 3) + lc;
            __half2 h0 = __floats2half2_rn(o[dn][0] * inv0, o[dn][1] * inv0);
            __half2 h1 = __floats2half2_rn(o[dn][2] * inv1, o[dn][3] * inv1);
            size_t ob0 = ((size_t)b * 512 + (2 * t0 + lpar)) * 1024
                       + (size_t)g * 512 + cbase + d;
            size_t ob1 = ((size_t)b * 512 + (2 * (t0 + 8) + lpar)) * 1024
                       + (size_t)g * 512 + cbase + d;
            *(__half2*)&atted[ob0] = h0;
            *(__half2*)&atted[ob1] = h1;
        }
    }
}

// ---------------------------------------------------------------------------
// Residual-add + LayerNorm over rows of 1024. One block (256 thr) per row.
// float4 loads/stores (each thread owns a contiguous quad).
// ---------------------------------------------------------------------------
__global__ __launch_bounds__(256)
void add_ln_kernel(const float* __restrict__ res, const float* __restrict__ dlt,
                   const float* __restrict__ gamma, const float* __restrict__ beta,
                   float* __restrict__ out, __half* __restrict__ outh)
{
    __shared__ float red[8];
    __shared__ float s_mean, s_inv;
    const int row = blockIdx.x;
    const int tid = threadIdx.x;
    const size_t base = (size_t)row * 1024;
    const int c0 = tid << 2;

    float4 xr = *(const float4*)&res[base + c0];
    float4 xd = *(const float4*)&dlt[base + c0];
    float x[4] = { xr.x + xd.x, xr.y + xd.y, xr.z + xd.z, xr.w + xd.w };
    float s = x[0] + x[1] + x[2] + x[3];
#pragma unroll
    for (int o = 16; o; o >>= 1) s += __shfl_xor_sync(0xffffffffu, s, o);
    if ((tid & 31) == 0) red[tid >> 5] = s;
    __syncthreads();
    if (tid < 32) {
        float t = (tid < 8) ? red[tid] : 0.f;
#pragma unroll
        for (int o = 4; o; o >>= 1) t += __shfl_xor_sync(0xffffffffu, t, o);
        if (tid == 0) s_mean = t * (1.f / 1024.f);
    }
    __syncthreads();
    const float mean = s_mean;

    float vs = 0.f;
#pragma unroll
    for (int i = 0; i < 4; i++) { float d = x[i] - mean; vs += d * d; }
#pragma unroll
    for (int o = 16; o; o >>= 1) vs += __shfl_xor_sync(0xffffffffu, vs, o);
    if ((tid & 31) == 0) red[tid >> 5] = vs;
    __syncthreads();
    if (tid < 32) {
        float t = (tid < 8) ? red[tid] : 0.f;
#pragma unroll
        for (int o = 4; o; o >>= 1) t += __shfl_xor_sync(0xffffffffu, t, o);
        if (tid == 0) s_inv = rsqrtf(t * (1.f / 1024.f) + 1e-6f);
    }
    __syncthreads();
    const float inv = s_inv;

    float4 gm = *(const float4*)&gamma[c0];
    float4 bt = *(const float4*)&beta[c0];
    float4 o4;
    o4.x = (x[0] - mean) * inv * gm.x + bt.x;
    o4.y = (x[1] - mean) * inv * gm.y + bt.y;
    o4.z = (x[2] - mean) * inv * gm.z + bt.z;
    o4.w = (x[3] - mean) * inv * gm.w + bt.w;
    *(float4*)&out[base + c0] = o4;
    if (outh) {
        __half2 h0 = __floats2half2_rn(o4.x, o4.y);
        __half2 h1 = __floats2half2_rn(o4.z, o4.w);
        *(__half2*)&outh[base + c0]     = h0;
        *(__half2*)&outh[base + c0 + 2] = h1;
    }
}

// ---------------------------------------------------------------------------
// Launch
// ---------------------------------------------------------------------------
extern "C" void kernel_launch(void* const* d_in, const int* in_sizes, int n_in,
                              void* d_out, int out_size)
{
    const float* y   = (const float*)d_in[0];
    const void*  msk = d_in[1];
    const float* Wv  = (const float*)d_in[2];
    const float* bv  = (const float*)d_in[3];
    const float* Wk  = (const float*)d_in[4];
    const float* bk  = (const float*)d_in[5];
    const float* Wq  = (const float*)d_in[6];
    const float* bq  = (const float*)d_in[7];
    const float* Wm  = (const float*)d_in[8];
    const float* bm  = (const float*)d_in[9];
    const float* W1  = (const float*)d_in[10];
    const float* b1  = (const float*)d_in[11];
    const float* W2  = (const float*)d_in[12];
    const float* b2  = (const float*)d_in[13];
    const float* g1  = (const float*)d_in[14];
    const float* be1 = (const float*)d_in[15];
    const float* g2  = (const float*)d_in[16];
    const float* be2 = (const float*)d_in[17];
    float* out = (float*)d_out;

    __half *yh, *wqkvT, *wmT, *w1T, *w2T, *qkv, *att, *y1h, *h1;
    float *bqkv, *mh, *y1, *ff;
    cudaGetSymbolAddress((void**)&yh,    g_yh);
    cudaGetSymbolAddress((void**)&wqkvT, g_wqkvT);
    cudaGetSymbolAddress((void**)&bqkv,  g_bqkv);
    cudaGetSymbolAddress((void**)&wmT,   g_wmT);
    cudaGetSymbolAddress((void**)&w1T,   g_w1T);
    cudaGetSymbolAddress((void**)&w2T,   g_w2T);
    cudaGetSymbolAddress((void**)&qkv,   g_qkv);
    cudaGetSymbolAddress((void**)&att,   g_att);
    cudaGetSymbolAddress((void**)&mh,    g_mh);
    cudaGetSymbolAddress((void**)&y1,    g_y1);
    cudaGetSymbolAddress((void**)&y1h,   g_y1h);
    cudaGetSymbolAddress((void**)&h1,    g_h1);
    cudaGetSymbolAddress((void**)&ff,    g_ff);

    cudaFuncSetAttribute(attn_mma,
                         cudaFuncAttributeMaxDynamicSharedMemorySize, ATTN_SMEM_BYTES);
    cudaFuncSetAttribute(hgemm<true,  false, true >,
                         cudaFuncAttributeMaxDynamicSharedMemorySize, GEMM_SMEM_BYTES);
    cudaFuncSetAttribute(hgemm<false, false, false>,
                         cudaFuncAttributeMaxDynamicSharedMemorySize, GEMM_SMEM_BYTES);
    cudaFuncSetAttribute(hgemm<false, true,  true >,
                         cudaFuncAttributeMaxDynamicSharedMemorySize, GEMM_SMEM_BYTES);

    dim3 blk(256);
    dim3 tblk(32, 8);

    // Pre-passes: y -> half; weights -> transposed (N,K) half; pack qkv bias
    cvt_half<<<2048, 512>>>(y, yh, 16*512*1024);
    transp_qkv<<<dim3(48, 16),  tblk>>>(Wq, Wk, Wv, wqkvT);
    pack_bias<<<3, 512>>>(bq, bk, bv, bqkv);
    transp<<<dim3(32, 32),  tblk>>>(Wm, wmT, 1024, 1024);
    transp<<<dim3(128, 32), tblk>>>(W1, w1T, 1024, 4096);
    transp<<<dim3(16, 64),  tblk>>>(W2, w2T, 2048, 512);

    // Fused QKV: (16384,1536) = gather(yh) @ Wqkv + bqkv  -> half
    hgemm<true,  false, true ><<<dim3(12, 128), blk, GEMM_SMEM_BYTES>>>(yh, wqkvT, bqkv, qkv, 16384, 1536, 512);

    // Tensor-core attention -> att (half, B,L,H layout)
    attn_mma<<<512, ATTN_THREADS, ATTN_SMEM_BYTES>>>(qkv, msk, att);

    // Merge: (8192,1024) @ Wm + bm -> fp32
    hgemm<false, false, false><<<dim3(8, 64), blk, GEMM_SMEM_BYTES>>>(att, wmT, bm, mh, 8192, 1024, 1024);

    // y1 = LN(y + merge): fp32 (residual) + half (FFN1 input)
    add_ln_kernel<<<8192, blk>>>(y, mh, g1, be1, y1, y1h);

    // FFN1: (8192,1024) @ W1 + b1, relu -> half
    hgemm<false, true,  true ><<<dim3(32, 64), blk, GEMM_SMEM_BYTES>>>(y1h, w1T, b1, h1, 8192, 4096, 1024);

    // FFN2 (grouped == contiguous reinterpret): (16384,2048) @ W2 + b2 -> fp32
    hgemm<false, false, false><<<dim3(4, 128), blk, GEMM_SMEM_BYTES>>>(h1, w2T, b2, ff, 16384, 512, 2048);

    // out = LN(y1 + ff), full fp32
    add_ln_kernel<<<8192, blk>>>(y1, ff, g2, be2, out, (__half*)0);
}